// round 1
// baseline (speedup 1.0000x reference)
#include <cuda_runtime.h>
#include <math.h>

#define VV 32000
#define DD 512
#define BB 8
#define SS 1024
#define BSZ (BB*SS)          // 8192
#define EPSV 1e-5f

// ---------------- scratch (static device allocations; no cudaMalloc) ----------------
__device__ float g_emb[(size_t)BSZ*DD];  // gathered embeddings; later reused nowhere
__device__ float g_f  [(size_t)BSZ*DD];  // forget gate (post-sigmoid)
__device__ float g_x  [(size_t)BSZ*DD];  // z1 -> xmix
__device__ float g_t  [(size_t)BSZ*DD];  // z2 temp
__device__ float g_xn [(size_t)BSZ*DD];  // scan output h, then final-LN'ed in place

// ---------------- 1. embedding gather ----------------
__global__ void k_gather(const int* __restrict__ tokens, const float* __restrict__ E) {
    int row = blockIdx.x;                       // 0..8191 (= b*S+s)
    int tok = tokens[row];
    const float4* src = (const float4*)(E + (size_t)tok * DD);
    float4* dst = (float4*)(g_emb + (size_t)row * DD);
    dst[threadIdx.x] = src[threadIdx.x];        // 128 threads * 16B = 2KB row
}

// ---------------- 2. phase-1 GEMMs: C[8192,512] = emb @ W, z selects {W_ih,W1,W2} ----
// W is [K=512, N=512] row-major (k-major), matching einsum 'bsd,de->bse'.
__global__ __launch_bounds__(256) void k_gemm_p1(
    const float* __restrict__ Wih, const float* __restrict__ bh,
    const float* __restrict__ W1,  const float* __restrict__ b1,
    const float* __restrict__ W2,  const float* __restrict__ b2)
{
    int z = blockIdx.z;
    const float* Bm   = (z==0) ? Wih : (z==1) ? W1 : W2;
    const float* bias = (z==0) ? bh  : (z==1) ? b1 : b2;
    float* Out        = (z==0) ? g_f : (z==1) ? g_x : g_t;

    __shared__ float As[8][128];
    __shared__ float Bs[8][128];
    int tid = threadIdx.x;
    int m0 = blockIdx.y * 128;
    int n0 = blockIdx.x * 128;
    int arow = tid >> 1, akq = (tid & 1) * 4;   // A loader: transpose into As[k][m]
    int bk = tid >> 5, bn = (tid & 31) * 4;     // B loader: direct Bs[k][n]
    int tx = tid & 15, ty = tid >> 4;

    float acc[8][8];
    #pragma unroll
    for (int i = 0; i < 8; i++)
        #pragma unroll
        for (int j = 0; j < 8; j++) acc[i][j] = 0.f;

    for (int k0 = 0; k0 < DD; k0 += 8) {
        float4 av = *(const float4*)(g_emb + (size_t)(m0 + arow) * DD + k0 + akq);
        float4 bv = *(const float4*)(Bm + (size_t)(k0 + bk) * DD + n0 + bn);
        __syncthreads();
        As[akq+0][arow] = av.x; As[akq+1][arow] = av.y;
        As[akq+2][arow] = av.z; As[akq+3][arow] = av.w;
        *(float4*)&Bs[bk][bn] = bv;
        __syncthreads();
        #pragma unroll
        for (int kk = 0; kk < 8; kk++) {
            float a[8], b[8];
            *(float4*)(a)   = *(const float4*)&As[kk][ty*8];
            *(float4*)(a+4) = *(const float4*)&As[kk][ty*8+4];
            *(float4*)(b)   = *(const float4*)&Bs[kk][tx*8];
            *(float4*)(b+4) = *(const float4*)&Bs[kk][tx*8+4];
            #pragma unroll
            for (int i = 0; i < 8; i++)
                #pragma unroll
                for (int j = 0; j < 8; j++)
                    acc[i][j] = fmaf(a[i], b[j], acc[i][j]);
        }
    }
    #pragma unroll
    for (int i = 0; i < 8; i++) {
        int m = m0 + ty*8 + i;
        #pragma unroll
        for (int j = 0; j < 8; j += 4) {
            int n = n0 + tx*8 + j;
            float4 o;
            o.x = acc[i][j+0] + bias[n+0];
            o.y = acc[i][j+1] + bias[n+1];
            o.z = acc[i][j+2] + bias[n+2];
            o.w = acc[i][j+3] + bias[n+3];
            if (z == 0) {  // forget gate: sigmoid
                o.x = 1.f/(1.f+expf(-o.x)); o.y = 1.f/(1.f+expf(-o.y));
                o.z = 1.f/(1.f+expf(-o.z)); o.w = 1.f/(1.f+expf(-o.w));
            }
            *(float4*)(Out + (size_t)m * DD + n) = o;
        }
    }
}

// ---------------- 3. combine: x = silu(z1) * z2 ----------------
__global__ void k_combine() {
    size_t i = (size_t)blockIdx.x * blockDim.x + threadIdx.x;   // over 1,048,576 float4
    float4 z1 = ((const float4*)g_x)[i];
    float4 z2 = ((const float4*)g_t)[i];
    float4 r;
    r.x = (z1.x / (1.f + expf(-z1.x))) * z2.x;
    r.y = (z1.y / (1.f + expf(-z1.y))) * z2.y;
    r.z = (z1.z / (1.f + expf(-z1.z))) * z2.z;
    r.w = (z1.w / (1.f + expf(-z1.w))) * z2.w;
    ((float4*)g_x)[i] = r;
}

// ---------------- 4. sequential scan: 1 warp per batch row ----------------
__device__ __forceinline__ void ldrow16(float* v, const float* p, int lane) {
    const float4* p4 = (const float4*)(p + lane * 16);
    #pragma unroll
    for (int i = 0; i < 4; i++) {
        float4 t = p4[i];
        v[i*4+0] = t.x; v[i*4+1] = t.y; v[i*4+2] = t.z; v[i*4+3] = t.w;
    }
}
__device__ __forceinline__ void strow16(float* p, const float* v, int lane) {
    float4* p4 = (float4*)(p + lane * 16);
    #pragma unroll
    for (int i = 0; i < 4; i++) {
        float4 t; t.x = v[i*4+0]; t.y = v[i*4+1]; t.z = v[i*4+2]; t.w = v[i*4+3];
        p4[i] = t;
    }
}

__global__ void k_scan(const float* __restrict__ h0,
                       const float* __restrict__ lng, const float* __restrict__ lnb) {
    int b = blockIdx.x, lane = threadIdx.x;
    float h[16], gw[16], gb[16];
    ldrow16(h,  h0,  lane);
    ldrow16(gw, lng, lane);
    ldrow16(gb, lnb, lane);
    size_t base = (size_t)b * SS * DD;

    float f[16], x[16];
    ldrow16(f, g_f + base, lane);
    ldrow16(x, g_x + base, lane);

    for (int s = 0; s < SS; s++) {
        // prefetch next step (independent of h -> hides latency behind reduction)
        float fn[16], xn[16];
        int sn = (s + 1 < SS) ? s + 1 : s;
        ldrow16(fn, g_f + base + (size_t)sn * DD, lane);
        ldrow16(xn, g_x + base + (size_t)sn * DD, lane);

        float hr[16];
        float s4[4] = {0,0,0,0}, q4[4] = {0,0,0,0};
        #pragma unroll
        for (int j = 0; j < 16; j++) {
            hr[j] = fmaf(f[j], h[j] - x[j], x[j]);   // f*h + (1-f)*x
            s4[j & 3] += hr[j];
            q4[j & 3] = fmaf(hr[j], hr[j], q4[j & 3]);
        }
        float sum = (s4[0] + s4[1]) + (s4[2] + s4[3]);
        float ssq = (q4[0] + q4[1]) + (q4[2] + q4[3]);
        #pragma unroll
        for (int o = 16; o; o >>= 1) {
            sum += __shfl_xor_sync(0xffffffffu, sum, o);
            ssq += __shfl_xor_sync(0xffffffffu, ssq, o);
        }
        float mean = sum * (1.f / DD);
        float var  = ssq * (1.f / DD) - mean * mean;
        float rstd = rsqrtf(var + EPSV);
        #pragma unroll
        for (int j = 0; j < 16; j++)
            h[j] = fmaf((hr[j] - mean) * rstd, gw[j], gb[j]) + h[j];

        strow16(g_xn + base + (size_t)s * DD, h, lane);  // raw h; final LN done later
        #pragma unroll
        for (int j = 0; j < 16; j++) { f[j] = fn[j]; x[j] = xn[j]; }
    }
}

// ---------------- 5. final layernorm over g_xn (in place), massively parallel ----
__global__ void k_finln(const float* __restrict__ lnfg, const float* __restrict__ lnfb) {
    int row  = blockIdx.x * 8 + (threadIdx.x >> 5);
    int lane = threadIdx.x & 31;
    float* p = g_xn + (size_t)row * DD;
    float v[16];
    ldrow16(v, p, lane);
    float s4[4] = {0,0,0,0}, q4[4] = {0,0,0,0};
    #pragma unroll
    for (int j = 0; j < 16; j++) {
        s4[j & 3] += v[j];
        q4[j & 3] = fmaf(v[j], v[j], q4[j & 3]);
    }
    float sum = (s4[0] + s4[1]) + (s4[2] + s4[3]);
    float ssq = (q4[0] + q4[1]) + (q4[2] + q4[3]);
    #pragma unroll
    for (int o = 16; o; o >>= 1) {
        sum += __shfl_xor_sync(0xffffffffu, sum, o);
        ssq += __shfl_xor_sync(0xffffffffu, ssq, o);
    }
    float mean = sum * (1.f / DD);
    float var  = ssq * (1.f / DD) - mean * mean;
    float rstd = rsqrtf(var + EPSV);
    float gw[16], gb[16];
    ldrow16(gw, lnfg, lane);
    ldrow16(gb, lnfb, lane);
    #pragma unroll
    for (int j = 0; j < 16; j++)
        v[j] = fmaf((v[j] - mean) * rstd, gw[j], gb[j]);
    strow16(p, v, lane);
}

// ---------------- 6. logits GEMM: out[8192,32000] = g_xn @ E^T ----------------
__global__ __launch_bounds__(256) void k_gemm_logits(const float* __restrict__ E,
                                                     float* __restrict__ out) {
    __shared__ float As[8][128];
    __shared__ float Bs[8][128];
    int tid = threadIdx.x;
    int n0 = blockIdx.x * 128;   // over V
    int m0 = blockIdx.y * 128;   // over B*S
    int arow = tid >> 1, akq = (tid & 1) * 4;
    int tx = tid & 15, ty = tid >> 4;

    float acc[8][8];
    #pragma unroll
    for (int i = 0; i < 8; i++)
        #pragma unroll
        for (int j = 0; j < 8; j++) acc[i][j] = 0.f;

    for (int k0 = 0; k0 < DD; k0 += 8) {
        float4 av = *(const float4*)(g_xn + (size_t)(m0 + arow) * DD + k0 + akq);
        float4 bv = *(const float4*)(E    + (size_t)(n0 + arow) * DD + k0 + akq);
        __syncthreads();
        As[akq+0][arow] = av.x; As[akq+1][arow] = av.y;
        As[akq+2][arow] = av.z; As[akq+3][arow] = av.w;
        Bs[akq+0][arow] = bv.x; Bs[akq+1][arow] = bv.y;
        Bs[akq+2][arow] = bv.z; Bs[akq+3][arow] = bv.w;
        __syncthreads();
        #pragma unroll
        for (int kk = 0; kk < 8; kk++) {
            float a[8], b[8];
            *(float4*)(a)   = *(const float4*)&As[kk][ty*8];
            *(float4*)(a+4) = *(const float4*)&As[kk][ty*8+4];
            *(float4*)(b)   = *(const float4*)&Bs[kk][tx*8];
            *(float4*)(b+4) = *(const float4*)&Bs[kk][tx*8+4];
            #pragma unroll
            for (int i = 0; i < 8; i++)
                #pragma unroll
                for (int j = 0; j < 8; j++)
                    acc[i][j] = fmaf(a[i], b[j], acc[i][j]);
        }
    }
    #pragma unroll
    for (int i = 0; i < 8; i++) {
        int m = m0 + ty*8 + i;
        #pragma unroll
        for (int j = 0; j < 8; j += 4) {
            int n = n0 + tx*8 + j;
            float4 o;
            o.x = acc[i][j+0]; o.y = acc[i][j+1];
            o.z = acc[i][j+2]; o.w = acc[i][j+3];
            *(float4*)(out + (size_t)m * VV + n) = o;
        }
    }
}

// ---------------- launch ----------------
extern "C" void kernel_launch(void* const* d_in, const int* in_sizes, int n_in,
                              void* d_out, int out_size) {
    const int*   tokens = (const int*)  d_in[0];
    const float* E      = (const float*)d_in[1];
    const float* W_ih   = (const float*)d_in[2];
    const float* b_h    = (const float*)d_in[3];
    const float* W1     = (const float*)d_in[4];
    const float* b1     = (const float*)d_in[5];
    const float* W2     = (const float*)d_in[6];
    const float* b2     = (const float*)d_in[7];
    const float* ln_g   = (const float*)d_in[8];
    const float* ln_b   = (const float*)d_in[9];
    const float* h0     = (const float*)d_in[10];
    const float* lnf_g  = (const float*)d_in[11];
    const float* lnf_b  = (const float*)d_in[12];
    float* out = (float*)d_out;

    k_gather<<<BSZ, 128>>>(tokens, E);
    k_gemm_p1<<<dim3(4, 64, 3), 256>>>(W_ih, b_h, W1, b1, W2, b2);
    k_combine<<<4096, 256>>>();
    k_scan<<<BB, 32>>>(h0, ln_g, ln_b);
    k_finln<<<BSZ/8, 256>>>(lnf_g, lnf_b);
    k_gemm_logits<<<dim3(VV/128, BSZ/128), 256>>>(E, out);
}

// round 3
// speedup vs baseline: 2.3605x; 2.3605x over previous
#include <cuda_runtime.h>
#include <math.h>
#include <stdint.h>

#define VV 32000
#define DD 512
#define BB 8
#define SS 1024
#define BSZ (BB*SS)          // 8192
#define EPSV 1e-5f

// ---------------- scratch (static device arrays; no cudaMalloc) ----------------
__device__ float g_emb[(size_t)BSZ*DD];
__device__ float g_f  [(size_t)BSZ*DD];
__device__ float g_x  [(size_t)BSZ*DD];
__device__ float g_t  [(size_t)BSZ*DD];
__device__ float g_xn [(size_t)BSZ*DD];

// ================= helpers =================
__device__ __forceinline__ float cvt_tf32(float x) {
    float r;
    asm("cvt.rna.tf32.f32 %0, %1;" : "=f"(r) : "f"(x));
    return r;
}
__device__ __forceinline__ float warp_sum(float v) {
    #pragma unroll
    for (int o = 16; o; o >>= 1) v += __shfl_xor_sync(0xffffffffu, v, o);
    return v;
}
// 32B-granularity swizzle: XOR bits[6:5] with row bits[1:0] (row stride = 128B)
__device__ __forceinline__ uint32_t swz(uint32_t byte_off) {
    return byte_off ^ (((byte_off >> 7) & 3u) << 5);
}
__device__ __forceinline__ void mma1688(float* c, const uint32_t* a, uint32_t b0, uint32_t b1) {
    asm volatile(
        "mma.sync.aligned.m16n8k8.row.col.f32.tf32.tf32.f32 "
        "{%0,%1,%2,%3}, {%4,%5,%6,%7}, {%8,%9}, {%0,%1,%2,%3};"
        : "+f"(c[0]), "+f"(c[1]), "+f"(c[2]), "+f"(c[3])
        : "r"(a[0]), "r"(a[1]), "r"(a[2]), "r"(a[3]), "r"(b0), "r"(b1));
}

// ---------------- 1. embedding gather ----------------
__global__ void k_gather(const int* __restrict__ tokens, const float* __restrict__ E) {
    int row = blockIdx.x;
    int tok = tokens[row];
    const float4* src = (const float4*)(E + (size_t)tok * DD);
    float4* dst = (float4*)(g_emb + (size_t)row * DD);
    dst[threadIdx.x] = src[threadIdx.x];
}

// ---------------- 2. phase-1 GEMMs (SIMT fp32, full precision) ----------------
__global__ __launch_bounds__(256) void k_gemm_p1(
    const float* __restrict__ Wih, const float* __restrict__ bh,
    const float* __restrict__ W1,  const float* __restrict__ b1,
    const float* __restrict__ W2,  const float* __restrict__ b2)
{
    int z = blockIdx.z;
    const float* Bm   = (z==0) ? Wih : (z==1) ? W1 : W2;
    const float* bias = (z==0) ? bh  : (z==1) ? b1 : b2;
    float* Out        = (z==0) ? g_f : (z==1) ? g_x : g_t;

    __shared__ float As[8][128];
    __shared__ float Bs[8][128];
    int tid = threadIdx.x;
    int m0 = blockIdx.y * 128;
    int n0 = blockIdx.x * 128;
    int arow = tid >> 1, akq = (tid & 1) * 4;
    int bk = tid >> 5, bn = (tid & 31) * 4;
    int tx = tid & 15, ty = tid >> 4;

    float acc[8][8];
    #pragma unroll
    for (int i = 0; i < 8; i++)
        #pragma unroll
        for (int j = 0; j < 8; j++) acc[i][j] = 0.f;

    for (int k0 = 0; k0 < DD; k0 += 8) {
        float4 av = *(const float4*)(g_emb + (size_t)(m0 + arow) * DD + k0 + akq);
        float4 bv = *(const float4*)(Bm + (size_t)(k0 + bk) * DD + n0 + bn);
        __syncthreads();
        As[akq+0][arow] = av.x; As[akq+1][arow] = av.y;
        As[akq+2][arow] = av.z; As[akq+3][arow] = av.w;
        *(float4*)&Bs[bk][bn] = bv;
        __syncthreads();
        #pragma unroll
        for (int kk = 0; kk < 8; kk++) {
            float a[8], b[8];
            *(float4*)(a)   = *(const float4*)&As[kk][ty*8];
            *(float4*)(a+4) = *(const float4*)&As[kk][ty*8+4];
            *(float4*)(b)   = *(const float4*)&Bs[kk][tx*8];
            *(float4*)(b+4) = *(const float4*)&Bs[kk][tx*8+4];
            #pragma unroll
            for (int i = 0; i < 8; i++)
                #pragma unroll
                for (int j = 0; j < 8; j++)
                    acc[i][j] = fmaf(a[i], b[j], acc[i][j]);
        }
    }
    #pragma unroll
    for (int i = 0; i < 8; i++) {
        int m = m0 + ty*8 + i;
        #pragma unroll
        for (int j = 0; j < 8; j += 4) {
            int n = n0 + tx*8 + j;
            float4 o;
            o.x = acc[i][j+0] + bias[n+0];
            o.y = acc[i][j+1] + bias[n+1];
            o.z = acc[i][j+2] + bias[n+2];
            o.w = acc[i][j+3] + bias[n+3];
            if (z == 0) {
                o.x = 1.f/(1.f+expf(-o.x)); o.y = 1.f/(1.f+expf(-o.y));
                o.z = 1.f/(1.f+expf(-o.z)); o.w = 1.f/(1.f+expf(-o.w));
            }
            *(float4*)(Out + (size_t)m * DD + n) = o;
        }
    }
}

// ---------------- 3. combine: x = silu(z1) * z2 ----------------
__global__ void k_combine() {
    size_t i = (size_t)blockIdx.x * blockDim.x + threadIdx.x;
    float4 z1 = ((const float4*)g_x)[i];
    float4 z2 = ((const float4*)g_t)[i];
    float4 r;
    r.x = (z1.x / (1.f + expf(-z1.x))) * z2.x;
    r.y = (z1.y / (1.f + expf(-z1.y))) * z2.y;
    r.z = (z1.z / (1.f + expf(-z1.z))) * z2.z;
    r.w = (z1.w / (1.f + expf(-z1.w))) * z2.w;
    ((float4*)g_x)[i] = r;
}

// ---------------- 4. sequential scan: 1 warp per batch, 4-deep prefetch ----------------
__device__ __forceinline__ void ldrow16(float* v, const float* p, int lane) {
    const float4* p4 = (const float4*)(p + lane * 16);
    #pragma unroll
    for (int i = 0; i < 4; i++) {
        float4 t = p4[i];
        v[i*4+0] = t.x; v[i*4+1] = t.y; v[i*4+2] = t.z; v[i*4+3] = t.w;
    }
}
__device__ __forceinline__ void strow16(float* p, const float* v, int lane) {
    float4* p4 = (float4*)(p + lane * 16);
    #pragma unroll
    for (int i = 0; i < 4; i++) {
        float4 t; t.x = v[i*4+0]; t.y = v[i*4+1]; t.z = v[i*4+2]; t.w = v[i*4+3];
        p4[i] = t;
    }
}

__global__ __launch_bounds__(32) void k_scan(const float* __restrict__ h0,
                       const float* __restrict__ lng, const float* __restrict__ lnb) {
    int b = blockIdx.x, lane = threadIdx.x;
    float h[16], gw[16], gb[16];
    ldrow16(h,  h0,  lane);
    ldrow16(gw, lng, lane);
    ldrow16(gb, lnb, lane);
    size_t base = (size_t)b * SS * DD;

    float fb[4][16], xb[4][16];
    #pragma unroll
    for (int p = 0; p < 4; p++) {
        ldrow16(fb[p], g_f + base + (size_t)p * DD, lane);
        ldrow16(xb[p], g_x + base + (size_t)p * DD, lane);
    }

    for (int s4 = 0; s4 < SS; s4 += 4) {
        #pragma unroll
        for (int u = 0; u < 4; u++) {
            int s = s4 + u;
            float hr[16];
            #pragma unroll
            for (int j = 0; j < 16; j++) {
                float Bv = fmaf(-fb[u][j], xb[u][j], xb[u][j]);  // off-chain
                hr[j] = fmaf(fb[u][j], h[j], Bv);
            }
            // prefetch s+4 into this slot (values consumed above)
            int sn = s + 4; if (sn >= SS) sn = SS - 1;
            ldrow16(fb[u], g_f + base + (size_t)sn * DD, lane);
            ldrow16(xb[u], g_x + base + (size_t)sn * DD, lane);

            float p4s[4] = {0,0,0,0}, q4s[4] = {0,0,0,0};
            #pragma unroll
            for (int j = 0; j < 16; j++) {
                p4s[j & 3] += hr[j];
                q4s[j & 3] = fmaf(hr[j], hr[j], q4s[j & 3]);
            }
            float sum = warp_sum((p4s[0] + p4s[1]) + (p4s[2] + p4s[3]));
            float ssq = warp_sum((q4s[0] + q4s[1]) + (q4s[2] + q4s[3]));
            float mean = sum * (1.f / DD);
            float var  = ssq * (1.f / DD) - mean * mean;
            float rstd = rsqrtf(var + EPSV);
            #pragma unroll
            for (int j = 0; j < 16; j++)
                h[j] = fmaf((hr[j] - mean) * rstd, gw[j], gb[j]) + h[j];

            strow16(g_xn + base + (size_t)s * DD, h, lane);
        }
    }
}

// ---------------- 5. final layernorm (parallel, in place) ----------------
__global__ void k_finln(const float* __restrict__ lnfg, const float* __restrict__ lnfb) {
    int row  = blockIdx.x * 8 + (threadIdx.x >> 5);
    int lane = threadIdx.x & 31;
    float* p = g_xn + (size_t)row * DD;
    float v[16];
    ldrow16(v, p, lane);
    float s4[4] = {0,0,0,0}, q4[4] = {0,0,0,0};
    #pragma unroll
    for (int j = 0; j < 16; j++) {
        s4[j & 3] += v[j];
        q4[j & 3] = fmaf(v[j], v[j], q4[j & 3]);
    }
    float sum = warp_sum((s4[0] + s4[1]) + (s4[2] + s4[3]));
    float ssq = warp_sum((q4[0] + q4[1]) + (q4[2] + q4[3]));
    float mean = sum * (1.f / DD);
    float var  = ssq * (1.f / DD) - mean * mean;
    float rstd = rsqrtf(var + EPSV);
    float gw[16], gb[16];
    ldrow16(gw, lnfg, lane);
    ldrow16(gb, lnfb, lane);
    #pragma unroll
    for (int j = 0; j < 16; j++)
        v[j] = fmaf((v[j] - mean) * rstd, gw[j], gb[j]);
    strow16(p, v, lane);
}

// ---------------- 6. logits GEMM via mma.sync tf32 ----------------
// out[8192,32000] = g_xn[8192,512] @ E[32000,512]^T
// CTA 128x128, 8 warps (2M x 4N), warp tile 64x32, K-chunk 32, double buffer.
// k-permutation inside each k8 fragment: frag col c -> physical k = (c<4)?2c:2(c-4)+1,
// applied to BOTH A and B, so fragment loads are contiguous float2 (LDS.64).
#define SMEM_LOGITS 65536

__global__ __launch_bounds__(256) void k_logits_mma(const float* __restrict__ E,
                                                    float* __restrict__ out) {
    extern __shared__ float sm[];   // [buf][A 4096 | B 4096] floats
    const int tid = threadIdx.x;
    const int wid = tid >> 5, lane = tid & 31;
    const int g = lane >> 2, t = lane & 3;
    const int warpM = wid >> 2, warpN = wid & 3;
    const int m0 = blockIdx.y * 128;
    const int n0 = blockIdx.x * 128;

    float acc[4][4][4];
    #pragma unroll
    for (int mt = 0; mt < 4; mt++)
        #pragma unroll
        for (int nt = 0; nt < 4; nt++)
            #pragma unroll
            for (int i = 0; i < 4; i++) acc[mt][nt][i] = 0.f;

    float4 ra[4], rb[4];
    const int lrow = tid >> 3, lq = tid & 7;   // loader: 256 threads cover 128 rows x 8 quads... (x2 iters)

    auto LDG = [&](int c) {
        int k0 = c * 32;
        #pragma unroll
        for (int it = 0; it < 4; it++) {
            int idx = it * 256 + tid;
            int row = idx >> 3, q = idx & 7;
            ra[it] = *(const float4*)(g_xn + (size_t)(m0 + row) * DD + k0 + q * 4);
            rb[it] = *(const float4*)(E    + (size_t)(n0 + row) * DD + k0 + q * 4);
        }
    };
    auto STS = [&](int buf) {
        char* bA = (char*)(sm + buf * 8192);
        char* bB = (char*)(sm + buf * 8192 + 4096);
        #pragma unroll
        for (int it = 0; it < 4; it++) {
            int idx = it * 256 + tid;
            int row = idx >> 3, q = idx & 7;
            uint32_t so = swz((uint32_t)(row * 128 + q * 16));
            float4 v = ra[it];
            v.x = cvt_tf32(v.x); v.y = cvt_tf32(v.y);
            v.z = cvt_tf32(v.z); v.w = cvt_tf32(v.w);
            *(float4*)(bA + so) = v;
            float4 w = rb[it];
            w.x = cvt_tf32(w.x); w.y = cvt_tf32(w.y);
            w.z = cvt_tf32(w.z); w.w = cvt_tf32(w.w);
            *(float4*)(bB + so) = w;
        }
    };
    auto COMP = [&](int buf) {
        const char* sA = (const char*)(sm + buf * 8192);
        const char* sB = (const char*)(sm + buf * 8192 + 4096);
        #pragma unroll
        for (int kk = 0; kk < 4; kk++) {
            uint32_t a[4][4];
            #pragma unroll
            for (int mt = 0; mt < 4; mt++) {
                int r0 = warpM * 64 + mt * 16 + g;
                uint32_t o1 = swz((uint32_t)(r0 * 128 + kk * 32 + t * 8));
                uint32_t o2 = swz((uint32_t)((r0 + 8) * 128 + kk * 32 + t * 8));
                float2 v1 = *(const float2*)(sA + o1);
                float2 v2 = *(const float2*)(sA + o2);
                a[mt][0] = __float_as_uint(v1.x);  // col t       -> k=2t
                a[mt][2] = __float_as_uint(v1.y);  // col t+4     -> k=2t+1
                a[mt][1] = __float_as_uint(v2.x);
                a[mt][3] = __float_as_uint(v2.y);
            }
            #pragma unroll
            for (int nt = 0; nt < 4; nt++) {
                int nr = warpN * 32 + nt * 8 + g;
                uint32_t o = swz((uint32_t)(nr * 128 + kk * 32 + t * 8));
                float2 bv = *(const float2*)(sB + o);
                uint32_t b0 = __float_as_uint(bv.x);  // row t   -> k=2t
                uint32_t b1 = __float_as_uint(bv.y);  // row t+4 -> k=2t+1
                #pragma unroll
                for (int mt = 0; mt < 4; mt++)
                    mma1688(acc[mt][nt], a[mt], b0, b1);
            }
        }
    };

    LDG(0); STS(0);
    __syncthreads();
    #pragma unroll 1
    for (int c = 0; c < 16; c++) {
        if (c + 1 < 16) LDG(c + 1);
        COMP(c & 1);
        if (c + 1 < 16) STS((c + 1) & 1);
        __syncthreads();
    }

    // epilogue: direct fp32 stores (float2 per fragment row)
    #pragma unroll
    for (int mt = 0; mt < 4; mt++) {
        int mrow = m0 + warpM * 64 + mt * 16 + g;
        #pragma unroll
        for (int nt = 0; nt < 4; nt++) {
            int ncol = n0 + warpN * 32 + nt * 8 + 2 * t;
            float2 lo; lo.x = acc[mt][nt][0]; lo.y = acc[mt][nt][1];
            float2 hi; hi.x = acc[mt][nt][2]; hi.y = acc[mt][nt][3];
            *(float2*)(out + (size_t)mrow * VV + ncol) = lo;
            *(float2*)(out + (size_t)(mrow + 8) * VV + ncol) = hi;
        }
    }
    (void)lrow; (void)lq;
}

// ---------------- launch ----------------
extern "C" void kernel_launch(void* const* d_in, const int* in_sizes, int n_in,
                              void* d_out, int out_size) {
    const int*   tokens = (const int*)  d_in[0];
    const float* E      = (const float*)d_in[1];
    const float* W_ih   = (const float*)d_in[2];
    const float* b_h    = (const float*)d_in[3];
    const float* W1     = (const float*)d_in[4];
    const float* b1     = (const float*)d_in[5];
    const float* W2     = (const float*)d_in[6];
    const float* b2     = (const float*)d_in[7];
    const float* ln_g   = (const float*)d_in[8];
    const float* ln_b   = (const float*)d_in[9];
    const float* h0     = (const float*)d_in[10];
    const float* lnf_g  = (const float*)d_in[11];
    const float* lnf_b  = (const float*)d_in[12];
    float* out = (float*)d_out;

    static int smem_set = 0;
    if (!smem_set) {
        cudaFuncSetAttribute(k_logits_mma, cudaFuncAttributeMaxDynamicSharedMemorySize,
                             SMEM_LOGITS);
        smem_set = 1;
    }

    k_gather<<<BSZ, 128>>>(tokens, E);
    k_gemm_p1<<<dim3(4, 64, 3), 256>>>(W_ih, b_h, W1, b1, W2, b2);
    k_combine<<<4096, 256>>>();
    k_scan<<<BB, 32>>>(h0, ln_g, ln_b);
    k_finln<<<BSZ/8, 256>>>(lnf_g, lnf_b);
    k_logits_mma<<<dim3(VV/128, BSZ/128), 256, SMEM_LOGITS>>>(E, out);
}

// round 4
// speedup vs baseline: 4.1789x; 1.7703x over previous
#include <cuda_runtime.h>
#include <cuda_fp16.h>
#include <math.h>
#include <stdint.h>

#define VV 32000
#define DD 512
#define BB 8
#define SS 1024
#define BSZ (BB*SS)          // 8192
#define EPSV 1e-5f

// ---------------- scratch (static device arrays; no cudaMalloc) ----------------
__device__ float  g_emb[(size_t)BSZ*DD];
__device__ float  g_f  [(size_t)BSZ*DD];
__device__ float  g_x  [(size_t)BSZ*DD];
__device__ float  g_t  [(size_t)BSZ*DD];
__device__ float  g_xn [(size_t)BSZ*DD];
__device__ __half g_xh [(size_t)BSZ*DD];   // final-LN output, fp16, k16-pair-permuted
__device__ __half g_Eh [(size_t)VV*DD];    // E, fp16, k16-pair-permuted

// ================= helpers =================
__device__ __forceinline__ float warp_sum(float v) {
    #pragma unroll
    for (int o = 16; o; o >>= 1) v += __shfl_xor_sync(0xffffffffu, v, o);
    return v;
}
// 32B-granularity swizzle for 128B rows: XOR bits[6:5] with row bits[1:0]
__device__ __forceinline__ uint32_t swz(uint32_t byte_off) {
    return byte_off ^ (((byte_off >> 7) & 3u) << 5);
}
__device__ __forceinline__ uint32_t smem_u32(const void* p) {
    uint32_t a;
    asm("{ .reg .u64 t; cvta.to.shared.u64 t, %1; cvt.u32.u64 %0, t; }" : "=r"(a) : "l"(p));
    return a;
}
__device__ __forceinline__ void cp16(uint32_t d, const void* s) {
    asm volatile("cp.async.cg.shared.global [%0], [%1], 16;" :: "r"(d), "l"(s) : "memory");
}
__device__ __forceinline__ void cpcommit() {
    asm volatile("cp.async.commit_group;" ::: "memory");
}
template<int N> __device__ __forceinline__ void cpwait() {
    asm volatile("cp.async.wait_group %0;" :: "n"(N) : "memory");
}
__device__ __forceinline__ void mma16816(float* c, const uint32_t* a, uint32_t b0, uint32_t b1) {
    asm volatile(
        "mma.sync.aligned.m16n8k16.row.col.f32.f16.f16.f32 "
        "{%0,%1,%2,%3}, {%4,%5,%6,%7}, {%8,%9}, {%0,%1,%2,%3};"
        : "+f"(c[0]), "+f"(c[1]), "+f"(c[2]), "+f"(c[3])
        : "r"(a[0]), "r"(a[1]), "r"(a[2]), "r"(a[3]), "r"(b0), "r"(b1));
}
// pack 16 logical floats (one k16 block) into 8 pair-permuted b32 halves
// phys pair j: logical pair p = (j&1) ? 4+(j>>1) : (j>>1)
__device__ __forceinline__ void pack_k16(const float* v, uint32_t* w) {
    #pragma unroll
    for (int j = 0; j < 8; j++) {
        int p = (j & 1) ? (4 + (j >> 1)) : (j >> 1);
        __half2 h = __floats2half2_rn(v[2*p], v[2*p+1]);   // low = k even
        w[j] = *(uint32_t*)&h;
    }
}

// ---------------- 0. E -> fp16 permuted ----------------
__global__ void k_conv_E(const float* __restrict__ E) {
    int idx = blockIdx.x * blockDim.x + threadIdx.x;   // over 32000*32 k16 blocks
    int n = idx >> 5, blk = idx & 31;
    const float* src = E + (size_t)n * DD + blk * 16;
    float v[16];
    #pragma unroll
    for (int i = 0; i < 4; i++) {
        float4 t = *(const float4*)(src + i * 4);
        v[i*4+0] = t.x; v[i*4+1] = t.y; v[i*4+2] = t.z; v[i*4+3] = t.w;
    }
    uint32_t w[8];
    pack_k16(v, w);
    uint4* dst = (uint4*)((char*)g_Eh + ((size_t)n * DD + blk * 16) * 2);
    dst[0] = make_uint4(w[0], w[1], w[2], w[3]);
    dst[1] = make_uint4(w[4], w[5], w[6], w[7]);
}

// ---------------- 1. embedding gather ----------------
__global__ void k_gather(const int* __restrict__ tokens, const float* __restrict__ E) {
    int row = blockIdx.x;
    int tok = tokens[row];
    const float4* src = (const float4*)(E + (size_t)tok * DD);
    float4* dst = (float4*)(g_emb + (size_t)row * DD);
    dst[threadIdx.x] = src[threadIdx.x];
}

// ---------------- 2. phase-1 GEMMs (SIMT fp32) ----------------
__global__ __launch_bounds__(256) void k_gemm_p1(
    const float* __restrict__ Wih, const float* __restrict__ bh,
    const float* __restrict__ W1,  const float* __restrict__ b1,
    const float* __restrict__ W2,  const float* __restrict__ b2)
{
    int z = blockIdx.z;
    const float* Bm   = (z==0) ? Wih : (z==1) ? W1 : W2;
    const float* bias = (z==0) ? bh  : (z==1) ? b1 : b2;
    float* Out        = (z==0) ? g_f : (z==1) ? g_x : g_t;

    __shared__ float As[8][128];
    __shared__ float Bs[8][128];
    int tid = threadIdx.x;
    int m0 = blockIdx.y * 128;
    int n0 = blockIdx.x * 128;
    int arow = tid >> 1, akq = (tid & 1) * 4;
    int bk = tid >> 5, bn = (tid & 31) * 4;
    int tx = tid & 15, ty = tid >> 4;

    float acc[8][8];
    #pragma unroll
    for (int i = 0; i < 8; i++)
        #pragma unroll
        for (int j = 0; j < 8; j++) acc[i][j] = 0.f;

    for (int k0 = 0; k0 < DD; k0 += 8) {
        float4 av = *(const float4*)(g_emb + (size_t)(m0 + arow) * DD + k0 + akq);
        float4 bv = *(const float4*)(Bm + (size_t)(k0 + bk) * DD + n0 + bn);
        __syncthreads();
        As[akq+0][arow] = av.x; As[akq+1][arow] = av.y;
        As[akq+2][arow] = av.z; As[akq+3][arow] = av.w;
        *(float4*)&Bs[bk][bn] = bv;
        __syncthreads();
        #pragma unroll
        for (int kk = 0; kk < 8; kk++) {
            float a[8], b[8];
            *(float4*)(a)   = *(const float4*)&As[kk][ty*8];
            *(float4*)(a+4) = *(const float4*)&As[kk][ty*8+4];
            *(float4*)(b)   = *(const float4*)&Bs[kk][tx*8];
            *(float4*)(b+4) = *(const float4*)&Bs[kk][tx*8+4];
            #pragma unroll
            for (int i = 0; i < 8; i++)
                #pragma unroll
                for (int j = 0; j < 8; j++)
                    acc[i][j] = fmaf(a[i], b[j], acc[i][j]);
        }
    }
    #pragma unroll
    for (int i = 0; i < 8; i++) {
        int m = m0 + ty*8 + i;
        #pragma unroll
        for (int j = 0; j < 8; j += 4) {
            int n = n0 + tx*8 + j;
            float4 o;
            o.x = acc[i][j+0] + bias[n+0];
            o.y = acc[i][j+1] + bias[n+1];
            o.z = acc[i][j+2] + bias[n+2];
            o.w = acc[i][j+3] + bias[n+3];
            if (z == 0) {
                o.x = 1.f/(1.f+expf(-o.x)); o.y = 1.f/(1.f+expf(-o.y));
                o.z = 1.f/(1.f+expf(-o.z)); o.w = 1.f/(1.f+expf(-o.w));
            }
            *(float4*)(Out + (size_t)m * DD + n) = o;
        }
    }
}

// ---------------- 3. combine: x = silu(z1) * z2 ----------------
__global__ void k_combine() {
    size_t i = (size_t)blockIdx.x * blockDim.x + threadIdx.x;
    float4 z1 = ((const float4*)g_x)[i];
    float4 z2 = ((const float4*)g_t)[i];
    float4 r;
    r.x = (z1.x / (1.f + expf(-z1.x))) * z2.x;
    r.y = (z1.y / (1.f + expf(-z1.y))) * z2.y;
    r.z = (z1.z / (1.f + expf(-z1.z))) * z2.z;
    r.w = (z1.w / (1.f + expf(-z1.w))) * z2.w;
    ((float4*)g_x)[i] = r;
}

// ---------------- 4. sequential scan: 1 warp per batch, 4-deep prefetch ----------------
__device__ __forceinline__ void ldrow16(float* v, const float* p, int lane) {
    const float4* p4 = (const float4*)(p + lane * 16);
    #pragma unroll
    for (int i = 0; i < 4; i++) {
        float4 t = p4[i];
        v[i*4+0] = t.x; v[i*4+1] = t.y; v[i*4+2] = t.z; v[i*4+3] = t.w;
    }
}
__device__ __forceinline__ void strow16(float* p, const float* v, int lane) {
    float4* p4 = (float4*)(p + lane * 16);
    #pragma unroll
    for (int i = 0; i < 4; i++) {
        float4 t; t.x = v[i*4+0]; t.y = v[i*4+1]; t.z = v[i*4+2]; t.w = v[i*4+3];
        p4[i] = t;
    }
}

__global__ __launch_bounds__(32) void k_scan(const float* __restrict__ h0,
                       const float* __restrict__ lng, const float* __restrict__ lnb) {
    int b = blockIdx.x, lane = threadIdx.x;
    float h[16], gw[16], gb[16];
    ldrow16(h,  h0,  lane);
    ldrow16(gw, lng, lane);
    ldrow16(gb, lnb, lane);
    size_t base = (size_t)b * SS * DD;

    float fb[4][16], xb[4][16];
    #pragma unroll
    for (int p = 0; p < 4; p++) {
        ldrow16(fb[p], g_f + base + (size_t)p * DD, lane);
        ldrow16(xb[p], g_x + base + (size_t)p * DD, lane);
    }

    for (int s4 = 0; s4 < SS; s4 += 4) {
        #pragma unroll
        for (int u = 0; u < 4; u++) {
            int s = s4 + u;
            float hr[16];
            #pragma unroll
            for (int j = 0; j < 16; j++) {
                float Bv = fmaf(-fb[u][j], xb[u][j], xb[u][j]);  // off-chain
                hr[j] = fmaf(fb[u][j], h[j], Bv);
            }
            int sn = s + 4; if (sn >= SS) sn = SS - 1;
            ldrow16(fb[u], g_f + base + (size_t)sn * DD, lane);
            ldrow16(xb[u], g_x + base + (size_t)sn * DD, lane);

            float p4s[4] = {0,0,0,0}, q4s[4] = {0,0,0,0};
            #pragma unroll
            for (int j = 0; j < 16; j++) {
                p4s[j & 3] += hr[j];
                q4s[j & 3] = fmaf(hr[j], hr[j], q4s[j & 3]);
            }
            float sum = warp_sum((p4s[0] + p4s[1]) + (p4s[2] + p4s[3]));
            float ssq = warp_sum((q4s[0] + q4s[1]) + (q4s[2] + q4s[3]));
            float mean = sum * (1.f / DD);
            float var  = ssq * (1.f / DD) - mean * mean;
            float rstd = rsqrtf(var + EPSV);
            #pragma unroll
            for (int j = 0; j < 16; j++)
                h[j] = fmaf((hr[j] - mean) * rstd, gw[j], gb[j]) + h[j];

            strow16(g_xn + base + (size_t)s * DD, h, lane);
        }
    }
}

// ---------------- 5. final layernorm -> fp16 permuted g_xh ----------------
__global__ void k_finln(const float* __restrict__ lnfg, const float* __restrict__ lnfb) {
    int row  = blockIdx.x * 8 + (threadIdx.x >> 5);
    int lane = threadIdx.x & 31;
    const float* p = g_xn + (size_t)row * DD;
    float v[16];
    ldrow16(v, p, lane);
    float s4[4] = {0,0,0,0}, q4[4] = {0,0,0,0};
    #pragma unroll
    for (int j = 0; j < 16; j++) {
        s4[j & 3] += v[j];
        q4[j & 3] = fmaf(v[j], v[j], q4[j & 3]);
    }
    float sum = warp_sum((s4[0] + s4[1]) + (s4[2] + s4[3]));
    float ssq = warp_sum((q4[0] + q4[1]) + (q4[2] + q4[3]));
    float mean = sum * (1.f / DD);
    float var  = ssq * (1.f / DD) - mean * mean;
    float rstd = rsqrtf(var + EPSV);
    float gw[16], gb[16];
    ldrow16(gw, lnfg, lane);
    ldrow16(gb, lnfb, lane);
    #pragma unroll
    for (int j = 0; j < 16; j++)
        v[j] = fmaf((v[j] - mean) * rstd, gw[j], gb[j]);
    // lane covers exactly one k16 block -> write 32B permuted fp16
    uint32_t w[8];
    pack_k16(v, w);
    uint4* dst = (uint4*)((char*)g_xh + ((size_t)row * DD + lane * 16) * 2);
    dst[0] = make_uint4(w[0], w[1], w[2], w[3]);
    dst[1] = make_uint4(w[4], w[5], w[6], w[7]);
}

// ---------------- 6. logits GEMM: fp16 mma + cp.async 3-stage pipeline ----------------
// out[8192,32000] = g_xh @ g_Eh^T. CTA 128x128, 8 warps (2Mx4N), warp 64x32.
// k-chunk 64 (128B rows), 8 chunks. smem: 3 stages x (A 16KB + B 16KB) = 96KB.
#define STAGE_BYTES 32768
#define SMEM_LOGITS (3*STAGE_BYTES)
#define NCHUNK 8

__global__ __launch_bounds__(256, 2) void k_logits_mma(float* __restrict__ out) {
    extern __shared__ char smem[];
    const uint32_t sb = smem_u32(smem);
    const int tid = threadIdx.x;
    const int wid = tid >> 5, lane = tid & 31;
    const int g = lane >> 2, t = lane & 3;
    const int warpM = wid >> 2, warpN = wid & 3;
    const int m0 = blockIdx.y * 128;
    const int n0 = blockIdx.x * 128;

    float acc[4][4][4];
    #pragma unroll
    for (int mt = 0; mt < 4; mt++)
        #pragma unroll
        for (int nt = 0; nt < 4; nt++)
            #pragma unroll
            for (int i = 0; i < 4; i++) acc[mt][nt][i] = 0.f;

    const char* gA = (const char*)g_xh + (size_t)m0 * DD * 2;
    const char* gB = (const char*)g_Eh + (size_t)n0 * DD * 2;

    auto LOAD = [&](int c) {
        uint32_t st = sb + (uint32_t)(c % 3) * STAGE_BYTES;
        int kb = c * 128;                       // byte offset of chunk within a 1KB row
        #pragma unroll
        for (int it = 0; it < 4; it++) {
            int idx = it * 256 + tid;
            int row = idx >> 3, q = idx & 7;
            uint32_t so = swz((uint32_t)(row * 128 + q * 16));
            cp16(st + so,         gA + (size_t)row * 1024 + kb + q * 16);
            cp16(st + 16384 + so, gB + (size_t)row * 1024 + kb + q * 16);
        }
        cpcommit();
    };

    auto COMP = [&](int buf) {
        const char* sA = smem + buf * STAGE_BYTES;
        const char* sB = smem + buf * STAGE_BYTES + 16384;
        #pragma unroll
        for (int kk = 0; kk < 4; kk++) {
            uint32_t a[4][4];
            #pragma unroll
            for (int mt = 0; mt < 4; mt++) {
                int r0 = warpM * 64 + mt * 16 + g;
                uint2 v1 = *(const uint2*)(sA + swz((uint32_t)(r0 * 128 + kk * 32 + t * 8)));
                uint2 v2 = *(const uint2*)(sA + swz((uint32_t)((r0 + 8) * 128 + kk * 32 + t * 8)));
                a[mt][0] = v1.x; a[mt][1] = v2.x; a[mt][2] = v1.y; a[mt][3] = v2.y;
            }
            #pragma unroll
            for (int nt = 0; nt < 4; nt++) {
                int nr = warpN * 32 + nt * 8 + g;
                uint2 bv = *(const uint2*)(sB + swz((uint32_t)(nr * 128 + kk * 32 + t * 8)));
                #pragma unroll
                for (int mt = 0; mt < 4; mt++)
                    mma16816(acc[mt][nt], a[mt], bv.x, bv.y);
            }
        }
    };

    LOAD(0); LOAD(1);
    #pragma unroll 1
    for (int c = 0; c < NCHUNK; c++) {
        if (c < NCHUNK - 1) cpwait<1>(); else cpwait<0>();
        __syncthreads();
        if (c + 2 < NCHUNK) LOAD(c + 2);
        COMP(c % 3);
    }

    #pragma unroll
    for (int mt = 0; mt < 4; mt++) {
        int mrow = m0 + warpM * 64 + mt * 16 + g;
        #pragma unroll
        for (int nt = 0; nt < 4; nt++) {
            int ncol = n0 + warpN * 32 + nt * 8 + 2 * t;
            float2 lo; lo.x = acc[mt][nt][0]; lo.y = acc[mt][nt][1];
            float2 hi; hi.x = acc[mt][nt][2]; hi.y = acc[mt][nt][3];
            *(float2*)(out + (size_t)mrow * VV + ncol) = lo;
            *(float2*)(out + (size_t)(mrow + 8) * VV + ncol) = hi;
        }
    }
}

// ---------------- launch ----------------
extern "C" void kernel_launch(void* const* d_in, const int* in_sizes, int n_in,
                              void* d_out, int out_size) {
    const int*   tokens = (const int*)  d_in[0];
    const float* E      = (const float*)d_in[1];
    const float* W_ih   = (const float*)d_in[2];
    const float* b_h    = (const float*)d_in[3];
    const float* W1     = (const float*)d_in[4];
    const float* b1     = (const float*)d_in[5];
    const float* W2     = (const float*)d_in[6];
    const float* b2     = (const float*)d_in[7];
    const float* ln_g   = (const float*)d_in[8];
    const float* ln_b   = (const float*)d_in[9];
    const float* h0     = (const float*)d_in[10];
    const float* lnf_g  = (const float*)d_in[11];
    const float* lnf_b  = (const float*)d_in[12];
    float* out = (float*)d_out;

    static int smem_set = 0;
    if (!smem_set) {
        cudaFuncSetAttribute(k_logits_mma, cudaFuncAttributeMaxDynamicSharedMemorySize,
                             SMEM_LOGITS);
        smem_set = 1;
    }

    k_conv_E<<<(VV*32)/256, 256>>>(E);
    k_gather<<<BSZ, 128>>>(tokens, E);
    k_gemm_p1<<<dim3(4, 64, 3), 256>>>(W_ih, b_h, W1, b1, W2, b2);
    k_combine<<<4096, 256>>>();
    k_scan<<<BB, 32>>>(h0, ln_g, ln_b);
    k_finln<<<BSZ/8, 256>>>(lnf_g, lnf_b);
    k_logits_mma<<<dim3(VV/128, BSZ/128), 256, SMEM_LOGITS>>>(out);
}

// round 5
// speedup vs baseline: 5.0071x; 1.1982x over previous
#include <cuda_runtime.h>
#include <cuda_fp16.h>
#include <math.h>
#include <stdint.h>

#define VV 32000
#define DD 512
#define BB 8
#define SS 1024
#define BSZ (BB*SS)          // 8192
#define EPSV 1e-5f

// ---------------- scratch (static device arrays; no cudaMalloc) ----------------
__device__ float  g_f  [(size_t)BSZ*DD];
__device__ float  g_x  [(size_t)BSZ*DD];
__device__ float  g_t  [(size_t)BSZ*DD];
__device__ float  g_xn [(size_t)BSZ*DD];
__device__ __half g_embh[(size_t)BSZ*DD];  // emb fp16 k16-pair-permuted
__device__ __half g_Wh [(size_t)3*DD*DD];  // W_ih/W1/W2 transposed [z][n][k] fp16 permuted
__device__ __half g_xh [(size_t)BSZ*DD];   // final-LN output fp16 permuted
__device__ __half g_Eh [(size_t)VV*DD];    // E fp16 permuted

// ================= helpers =================
__device__ __forceinline__ float warp_sum(float v) {
    #pragma unroll
    for (int o = 16; o; o >>= 1) v += __shfl_xor_sync(0xffffffffu, v, o);
    return v;
}
__device__ __forceinline__ uint32_t swz(uint32_t byte_off) {
    return byte_off ^ (((byte_off >> 7) & 3u) << 5);
}
__device__ __forceinline__ uint32_t smem_u32(const void* p) {
    uint32_t a;
    asm("{ .reg .u64 t; cvta.to.shared.u64 t, %1; cvt.u32.u64 %0, t; }" : "=r"(a) : "l"(p));
    return a;
}
__device__ __forceinline__ void cp16(uint32_t d, const void* s) {
    asm volatile("cp.async.cg.shared.global [%0], [%1], 16;" :: "r"(d), "l"(s) : "memory");
}
__device__ __forceinline__ void cpcommit() {
    asm volatile("cp.async.commit_group;" ::: "memory");
}
template<int N> __device__ __forceinline__ void cpwait() {
    asm volatile("cp.async.wait_group %0;" :: "n"(N) : "memory");
}
__device__ __forceinline__ void mma16816(float* c, const uint32_t* a, uint32_t b0, uint32_t b1) {
    asm volatile(
        "mma.sync.aligned.m16n8k16.row.col.f32.f16.f16.f32 "
        "{%0,%1,%2,%3}, {%4,%5,%6,%7}, {%8,%9}, {%0,%1,%2,%3};"
        : "+f"(c[0]), "+f"(c[1]), "+f"(c[2]), "+f"(c[3])
        : "r"(a[0]), "r"(a[1]), "r"(a[2]), "r"(a[3]), "r"(b0), "r"(b1));
}
// pack 16 logical floats (one k16 block) into 8 pair-permuted b32 halves
__device__ __forceinline__ void pack_k16(const float* v, uint32_t* w) {
    #pragma unroll
    for (int j = 0; j < 8; j++) {
        int p = (j & 1) ? (4 + (j >> 1)) : (j >> 1);
        __half2 h = __floats2half2_rn(v[2*p], v[2*p+1]);
        w[j] = *(uint32_t*)&h;
    }
}

// ---------------- 0a. E -> fp16 permuted ----------------
__global__ void k_conv_E(const float* __restrict__ E) {
    int idx = blockIdx.x * blockDim.x + threadIdx.x;   // over 32000*32 k16 blocks
    int n = idx >> 5, blk = idx & 31;
    const float* src = E + (size_t)n * DD + blk * 16;
    float v[16];
    #pragma unroll
    for (int i = 0; i < 4; i++) {
        float4 t = *(const float4*)(src + i * 4);
        v[i*4+0] = t.x; v[i*4+1] = t.y; v[i*4+2] = t.z; v[i*4+3] = t.w;
    }
    uint32_t w[8];
    pack_k16(v, w);
    uint4* dst = (uint4*)((char*)g_Eh + ((size_t)n * DD + blk * 16) * 2);
    dst[0] = make_uint4(w[0], w[1], w[2], w[3]);
    dst[1] = make_uint4(w[4], w[5], w[6], w[7]);
}

// ---------------- 0b. W_ih/W1/W2 -> transposed fp16 permuted [z][n][k] ----------------
__global__ void k_conv_W(const float* __restrict__ Wih, const float* __restrict__ W1,
                         const float* __restrict__ W2) {
    int t = blockIdx.x * blockDim.x + threadIdx.x;     // 3*512*32
    int z = t / (DD * 32);
    int rem = t % (DD * 32);
    int n = rem >> 5, blk = rem & 31;
    const float* W = (z == 0) ? Wih : (z == 1) ? W1 : W2;
    float v[16];
    #pragma unroll
    for (int kk = 0; kk < 16; kk++)
        v[kk] = W[(size_t)(blk * 16 + kk) * DD + n];   // W[k][n]
    uint32_t w[8];
    pack_k16(v, w);
    uint4* dst = (uint4*)((char*)g_Wh + (((size_t)z * DD + n) * DD + blk * 16) * 2);
    dst[0] = make_uint4(w[0], w[1], w[2], w[3]);
    dst[1] = make_uint4(w[4], w[5], w[6], w[7]);
}

// ---------------- 1. embedding gather -> fp16 permuted ----------------
__global__ void k_gather(const int* __restrict__ tokens, const float* __restrict__ E) {
    int row = blockIdx.x * 8 + (threadIdx.x >> 5);
    int lane = threadIdx.x & 31;
    int tok = tokens[row];
    const float* src = E + (size_t)tok * DD + lane * 16;
    float v[16];
    #pragma unroll
    for (int i = 0; i < 4; i++) {
        float4 t = *(const float4*)(src + i * 4);
        v[i*4+0] = t.x; v[i*4+1] = t.y; v[i*4+2] = t.z; v[i*4+3] = t.w;
    }
    uint32_t w[8];
    pack_k16(v, w);
    uint4* dst = (uint4*)((char*)g_embh + ((size_t)row * DD + lane * 16) * 2);
    dst[0] = make_uint4(w[0], w[1], w[2], w[3]);
    dst[1] = make_uint4(w[4], w[5], w[6], w[7]);
}

// ---------------- 2. phase-1 GEMMs via fp16 mma (fused 3x) ----------------
// [8192,512] x [512,512]^T(xposed) for z in {0,1,2}. CTA 128x128, 8 warps.
#define STAGE_BYTES 32768
#define SMEM_MMA (3*STAGE_BYTES)
#define NCHUNK 8

__global__ __launch_bounds__(256, 2) void k_p1_mma(
    const float* __restrict__ bh, const float* __restrict__ b1f,
    const float* __restrict__ b2f)
{
    extern __shared__ char smem[];
    const uint32_t sb = smem_u32(smem);
    const int tid = threadIdx.x;
    const int wid = tid >> 5, lane = tid & 31;
    const int g = lane >> 2, t = lane & 3;
    const int warpM = wid >> 2, warpN = wid & 3;
    const int m0 = blockIdx.y * 128;
    const int z = blockIdx.x >> 2;
    const int nloc0 = (blockIdx.x & 3) * 128;
    const float* bias = (z == 0) ? bh : (z == 1) ? b1f : b2f;
    float* Out = (z == 0) ? g_f : (z == 1) ? g_x : g_t;

    float acc[4][4][4];
    #pragma unroll
    for (int mt = 0; mt < 4; mt++)
        #pragma unroll
        for (int nt = 0; nt < 4; nt++)
            #pragma unroll
            for (int i = 0; i < 4; i++) acc[mt][nt][i] = 0.f;

    const char* gA = (const char*)g_embh + (size_t)m0 * DD * 2;
    const char* gB = (const char*)g_Wh + ((size_t)z * DD + nloc0) * DD * 2;

    auto LOAD = [&](int c) {
        uint32_t st = sb + (uint32_t)(c % 3) * STAGE_BYTES;
        int kb = c * 128;
        #pragma unroll
        for (int it = 0; it < 4; it++) {
            int idx = it * 256 + tid;
            int row = idx >> 3, q = idx & 7;
            uint32_t so = swz((uint32_t)(row * 128 + q * 16));
            cp16(st + so,         gA + (size_t)row * 1024 + kb + q * 16);
            cp16(st + 16384 + so, gB + (size_t)row * 1024 + kb + q * 16);
        }
        cpcommit();
    };
    auto COMP = [&](int buf) {
        const char* sA = smem + buf * STAGE_BYTES;
        const char* sB = smem + buf * STAGE_BYTES + 16384;
        #pragma unroll
        for (int kk = 0; kk < 4; kk++) {
            uint32_t a[4][4];
            #pragma unroll
            for (int mt = 0; mt < 4; mt++) {
                int r0 = warpM * 64 + mt * 16 + g;
                uint2 v1 = *(const uint2*)(sA + swz((uint32_t)(r0 * 128 + kk * 32 + t * 8)));
                uint2 v2 = *(const uint2*)(sA + swz((uint32_t)((r0 + 8) * 128 + kk * 32 + t * 8)));
                a[mt][0] = v1.x; a[mt][1] = v2.x; a[mt][2] = v1.y; a[mt][3] = v2.y;
            }
            #pragma unroll
            for (int nt = 0; nt < 4; nt++) {
                int nr = warpN * 32 + nt * 8 + g;
                uint2 bv = *(const uint2*)(sB + swz((uint32_t)(nr * 128 + kk * 32 + t * 8)));
                #pragma unroll
                for (int mt = 0; mt < 4; mt++)
                    mma16816(acc[mt][nt], a[mt], bv.x, bv.y);
            }
        }
    };

    LOAD(0); LOAD(1);
    #pragma unroll 1
    for (int c = 0; c < NCHUNK; c++) {
        if (c < NCHUNK - 1) cpwait<1>(); else cpwait<0>();
        __syncthreads();
        if (c + 2 < NCHUNK) LOAD(c + 2);
        COMP(c % 3);
    }

    #pragma unroll
    for (int mt = 0; mt < 4; mt++) {
        int mrow = m0 + warpM * 64 + mt * 16 + g;
        #pragma unroll
        for (int nt = 0; nt < 4; nt++) {
            int nl = nloc0 + warpN * 32 + nt * 8 + 2 * t;
            float bx = bias[nl], by = bias[nl + 1];
            float2 lo, hi;
            lo.x = acc[mt][nt][0] + bx; lo.y = acc[mt][nt][1] + by;
            hi.x = acc[mt][nt][2] + bx; hi.y = acc[mt][nt][3] + by;
            if (z == 0) {
                lo.x = 1.f/(1.f+expf(-lo.x)); lo.y = 1.f/(1.f+expf(-lo.y));
                hi.x = 1.f/(1.f+expf(-hi.x)); hi.y = 1.f/(1.f+expf(-hi.y));
            }
            *(float2*)(Out + (size_t)mrow * DD + nl) = lo;
            *(float2*)(Out + (size_t)(mrow + 8) * DD + nl) = hi;
        }
    }
}

// ---------------- 3. combine: x = silu(z1) * z2 ----------------
__global__ void k_combine() {
    size_t i = (size_t)blockIdx.x * blockDim.x + threadIdx.x;
    float4 z1 = ((const float4*)g_x)[i];
    float4 z2 = ((const float4*)g_t)[i];
    float4 r;
    r.x = (z1.x / (1.f + expf(-z1.x))) * z2.x;
    r.y = (z1.y / (1.f + expf(-z1.y))) * z2.y;
    r.z = (z1.z / (1.f + expf(-z1.z))) * z2.z;
    r.w = (z1.w / (1.f + expf(-z1.w))) * z2.w;
    ((float4*)g_x)[i] = r;
}

// ---------------- 4. scan: 1 warp/batch, cp.async smem ring ----------------
// element mapping: lane holds elems j = i*128 + lane*4 + c (i,c in 0..3)
__global__ __launch_bounds__(32) void k_scan(const float* __restrict__ h0,
                       const float* __restrict__ lng, const float* __restrict__ lnb) {
    __shared__ float ring[8][1024];   // [stage][0..511]=f, [512..1023]=x
    int b = blockIdx.x, lane = threadIdx.x;
    size_t base = (size_t)b * SS * DD;

    auto issue = [&](int s) {
        if (s < SS) {
            uint32_t dst = smem_u32(&ring[s & 7][0]);
            const float* fs = g_f + base + (size_t)s * DD;
            const float* xs = g_x + base + (size_t)s * DD;
            #pragma unroll
            for (int i = 0; i < 4; i++) {
                int c = i * 32 + lane;
                cp16(dst + c * 16,        fs + c * 4);
                cp16(dst + 2048 + c * 16, xs + c * 4);
            }
        }
        cpcommit();
    };
    #pragma unroll
    for (int p = 0; p < 6; p++) issue(p);

    float h[16], gw[16], gb[16], e[16];
    #pragma unroll
    for (int i = 0; i < 4; i++) {
        int off = i * 128 + lane * 4;
        *(float4*)(h  + i*4) = *(const float4*)(h0  + off);
        *(float4*)(gw + i*4) = *(const float4*)(lng + off);
        *(float4*)(gb + i*4) = *(const float4*)(lnb + off);
    }
    #pragma unroll
    for (int j = 0; j < 16; j++) e[j] = gb[j] + h[j];

    // preload step 0
    cpwait<5>();
    float fc[16], Bv[16];
    #pragma unroll
    for (int i = 0; i < 4; i++) {
        int off = i * 128 + lane * 4;
        float4 fv = *(const float4*)(&ring[0][off]);
        float4 xv = *(const float4*)(&ring[0][512 + off]);
        fc[i*4+0]=fv.x; fc[i*4+1]=fv.y; fc[i*4+2]=fv.z; fc[i*4+3]=fv.w;
        Bv[i*4+0]=fmaf(-fv.x,xv.x,xv.x); Bv[i*4+1]=fmaf(-fv.y,xv.y,xv.y);
        Bv[i*4+2]=fmaf(-fv.z,xv.z,xv.z); Bv[i*4+3]=fmaf(-fv.w,xv.w,xv.w);
    }

    #pragma unroll 1
    for (int s = 0; s < SS; s++) {
        float hr[16];
        #pragma unroll
        for (int j = 0; j < 16; j++) hr[j] = fmaf(fc[j], h[j], Bv[j]);

        float p4s[4] = {0,0,0,0}, q4s[4] = {0,0,0,0};
        #pragma unroll
        for (int j = 0; j < 16; j++) {
            p4s[j & 3] += hr[j];
            q4s[j & 3] = fmaf(hr[j], hr[j], q4s[j & 3]);
        }
        float sum = (p4s[0] + p4s[1]) + (p4s[2] + p4s[3]);
        float ssq = (q4s[0] + q4s[1]) + (q4s[2] + q4s[3]);
        #pragma unroll
        for (int o = 16; o; o >>= 1) {
            sum += __shfl_xor_sync(0xffffffffu, sum, o);
            ssq += __shfl_xor_sync(0xffffffffu, ssq, o);
        }

        // (issued while shfls are in flight, scheduled by ptxas)
        issue(s + 6);
        float hg[16];
        #pragma unroll
        for (int j = 0; j < 16; j++) hg[j] = hr[j] * gw[j];

        cpwait<5>();                      // stage s+1 ready
        float fn[16], Bn[16];
        if (s + 1 < SS) {
            const float* rg = &ring[(s + 1) & 7][0];
            #pragma unroll
            for (int i = 0; i < 4; i++) {
                int off = i * 128 + lane * 4;
                float4 fv = *(const float4*)(rg + off);
                float4 xv = *(const float4*)(rg + 512 + off);
                fn[i*4+0]=fv.x; fn[i*4+1]=fv.y; fn[i*4+2]=fv.z; fn[i*4+3]=fv.w;
                Bn[i*4+0]=fmaf(-fv.x,xv.x,xv.x); Bn[i*4+1]=fmaf(-fv.y,xv.y,xv.y);
                Bn[i*4+2]=fmaf(-fv.z,xv.z,xv.z); Bn[i*4+3]=fmaf(-fv.w,xv.w,xv.w);
            }
        }

        float mean = sum * (1.f / DD);
        float var  = fmaf(-mean, mean, ssq * (1.f / DD));
        float rstd = rsqrtf(var + EPSV);
        float t1   = mean * rstd;
        #pragma unroll
        for (int j = 0; j < 16; j++)
            h[j] = fmaf(hg[j], rstd, fmaf(gw[j], -t1, e[j]));

        float* dst = g_xn + base + (size_t)s * DD;
        #pragma unroll
        for (int i = 0; i < 4; i++)
            *(float4*)(dst + i * 128 + lane * 4) = *(float4*)(h + i * 4);

        #pragma unroll
        for (int j = 0; j < 16; j++) {
            e[j] = gb[j] + h[j];
            fc[j] = fn[j]; Bv[j] = Bn[j];
        }
    }
}

// ---------------- 5. final layernorm -> fp16 permuted g_xh ----------------
__device__ __forceinline__ void ldrow16(float* v, const float* p, int lane) {
    const float4* p4 = (const float4*)(p + lane * 16);
    #pragma unroll
    for (int i = 0; i < 4; i++) {
        float4 t = p4[i];
        v[i*4+0] = t.x; v[i*4+1] = t.y; v[i*4+2] = t.z; v[i*4+3] = t.w;
    }
}
__global__ void k_finln(const float* __restrict__ lnfg, const float* __restrict__ lnfb) {
    int row  = blockIdx.x * 8 + (threadIdx.x >> 5);
    int lane = threadIdx.x & 31;
    const float* p = g_xn + (size_t)row * DD;
    float v[16];
    ldrow16(v, p, lane);
    float s4[4] = {0,0,0,0}, q4[4] = {0,0,0,0};
    #pragma unroll
    for (int j = 0; j < 16; j++) {
        s4[j & 3] += v[j];
        q4[j & 3] = fmaf(v[j], v[j], q4[j & 3]);
    }
    float sum = warp_sum((s4[0] + s4[1]) + (s4[2] + s4[3]));
    float ssq = warp_sum((q4[0] + q4[1]) + (q4[2] + q4[3]));
    float mean = sum * (1.f / DD);
    float var  = ssq * (1.f / DD) - mean * mean;
    float rstd = rsqrtf(var + EPSV);
    float gw[16], gb[16];
    ldrow16(gw, lnfg, lane);
    ldrow16(gb, lnfb, lane);
    #pragma unroll
    for (int j = 0; j < 16; j++)
        v[j] = fmaf((v[j] - mean) * rstd, gw[j], gb[j]);
    uint32_t w[8];
    pack_k16(v, w);
    uint4* dst = (uint4*)((char*)g_xh + ((size_t)row * DD + lane * 16) * 2);
    dst[0] = make_uint4(w[0], w[1], w[2], w[3]);
    dst[1] = make_uint4(w[4], w[5], w[6], w[7]);
}

// ---------------- 6. logits GEMM: fp16 mma, panel-remapped grid ----------------
#define NT_LOG 250
#define PANEL 8

__global__ __launch_bounds__(256, 2) void k_logits_mma(float* __restrict__ out) {
    extern __shared__ char smem[];
    const uint32_t sb = smem_u32(smem);
    const int tid = threadIdx.x;
    const int wid = tid >> 5, lane = tid & 31;
    const int g = lane >> 2, t = lane & 3;
    const int warpM = wid >> 2, warpN = wid & 3;
    int pid = blockIdx.x;
    int panel = pid / (PANEL * NT_LOG);
    int rem = pid % (PANEL * NT_LOG);
    const int m0 = (panel * PANEL + (rem % PANEL)) * 128;
    const int n0 = (rem / PANEL) * 128;

    float acc[4][4][4];
    #pragma unroll
    for (int mt = 0; mt < 4; mt++)
        #pragma unroll
        for (int nt = 0; nt < 4; nt++)
            #pragma unroll
            for (int i = 0; i < 4; i++) acc[mt][nt][i] = 0.f;

    const char* gA = (const char*)g_xh + (size_t)m0 * DD * 2;
    const char* gB = (const char*)g_Eh + (size_t)n0 * DD * 2;

    auto LOAD = [&](int c) {
        uint32_t st = sb + (uint32_t)(c % 3) * STAGE_BYTES;
        int kb = c * 128;
        #pragma unroll
        for (int it = 0; it < 4; it++) {
            int idx = it * 256 + tid;
            int row = idx >> 3, q = idx & 7;
            uint32_t so = swz((uint32_t)(row * 128 + q * 16));
            cp16(st + so,         gA + (size_t)row * 1024 + kb + q * 16);
            cp16(st + 16384 + so, gB + (size_t)row * 1024 + kb + q * 16);
        }
        cpcommit();
    };
    auto COMP = [&](int buf) {
        const char* sA = smem + buf * STAGE_BYTES;
        const char* sB = smem + buf * STAGE_BYTES + 16384;
        #pragma unroll
        for (int kk = 0; kk < 4; kk++) {
            uint32_t a[4][4];
            #pragma unroll
            for (int mt = 0; mt < 4; mt++) {
                int r0 = warpM * 64 + mt * 16 + g;
                uint2 v1 = *(const uint2*)(sA + swz((uint32_t)(r0 * 128 + kk * 32 + t * 8)));
                uint2 v2 = *(const uint2*)(sA + swz((uint32_t)((r0 + 8) * 128 + kk * 32 + t * 8)));
                a[mt][0] = v1.x; a[mt][1] = v2.x; a[mt][2] = v1.y; a[mt][3] = v2.y;
            }
            #pragma unroll
            for (int nt = 0; nt < 4; nt++) {
                int nr = warpN * 32 + nt * 8 + g;
                uint2 bv = *(const uint2*)(sB + swz((uint32_t)(nr * 128 + kk * 32 + t * 8)));
                #pragma unroll
                for (int mt = 0; mt < 4; mt++)
                    mma16816(acc[mt][nt], a[mt], bv.x, bv.y);
            }
        }
    };

    LOAD(0); LOAD(1);
    #pragma unroll 1
    for (int c = 0; c < NCHUNK; c++) {
        if (c < NCHUNK - 1) cpwait<1>(); else cpwait<0>();
        __syncthreads();
        if (c + 2 < NCHUNK) LOAD(c + 2);
        COMP(c % 3);
    }

    #pragma unroll
    for (int mt = 0; mt < 4; mt++) {
        int mrow = m0 + warpM * 64 + mt * 16 + g;
        #pragma unroll
        for (int nt = 0; nt < 4; nt++) {
            int ncol = n0 + warpN * 32 + nt * 8 + 2 * t;
            float2 lo; lo.x = acc[mt][nt][0]; lo.y = acc[mt][nt][1];
            float2 hi; hi.x = acc[mt][nt][2]; hi.y = acc[mt][nt][3];
            *(float2*)(out + (size_t)mrow * VV + ncol) = lo;
            *(float2*)(out + (size_t)(mrow + 8) * VV + ncol) = hi;
        }
    }
}

// ---------------- launch ----------------
extern "C" void kernel_launch(void* const* d_in, const int* in_sizes, int n_in,
                              void* d_out, int out_size) {
    const int*   tokens = (const int*)  d_in[0];
    const float* E      = (const float*)d_in[1];
    const float* W_ih   = (const float*)d_in[2];
    const float* b_h    = (const float*)d_in[3];
    const float* W1     = (const float*)d_in[4];
    const float* b1     = (const float*)d_in[5];
    const float* W2     = (const float*)d_in[6];
    const float* b2     = (const float*)d_in[7];
    const float* ln_g   = (const float*)d_in[8];
    const float* ln_b   = (const float*)d_in[9];
    const float* h0     = (const float*)d_in[10];
    const float* lnf_g  = (const float*)d_in[11];
    const float* lnf_b  = (const float*)d_in[12];
    float* out = (float*)d_out;

    static int smem_set = 0;
    if (!smem_set) {
        cudaFuncSetAttribute(k_logits_mma, cudaFuncAttributeMaxDynamicSharedMemorySize, SMEM_MMA);
        cudaFuncSetAttribute(k_p1_mma, cudaFuncAttributeMaxDynamicSharedMemorySize, SMEM_MMA);
        smem_set = 1;
    }

    k_conv_E<<<(VV*32)/256, 256>>>(E);
    k_conv_W<<<(3*DD*32)/256, 256>>>(W_ih, W1, W2);
    k_gather<<<BSZ/8, 256>>>(tokens, E);
    k_p1_mma<<<dim3(12, 64), 256, SMEM_MMA>>>(b_h, b1, b2);
    k_combine<<<4096, 256>>>();
    k_scan<<<BB, 32>>>(h0, ln_g, ln_b);
    k_finln<<<BSZ/8, 256>>>(lnf_g, lnf_b);
    k_logits_mma<<<64*NT_LOG, 256, SMEM_MMA>>>(out);
}

// round 8
// speedup vs baseline: 5.0882x; 1.0162x over previous
#include <cuda_runtime.h>
#include <cuda_fp16.h>
#include <math.h>
#include <stdint.h>

#define VV 32000
#define DD 512
#define BB 8
#define SS 1024
#define BSZ (BB*SS)          // 8192
#define EPSV 1e-5f
#define NSEG 8
#define SEGLEN (SS/NSEG)     // 128
#define NTILE_N 250
#define NTILES (NSEG*NTILE_N*BB)   // 16000

// ---------------- scratch (static device arrays; no cudaMalloc) ----------------
__device__ float  g_f  [(size_t)BSZ*DD];
__device__ float  g_x  [(size_t)BSZ*DD];
__device__ float  g_t  [(size_t)BSZ*DD];
__device__ float  g_xn [(size_t)BSZ*DD];
__device__ __half g_embh[(size_t)BSZ*DD];  // emb fp16 k16-pair-permuted
__device__ __half g_Wh [(size_t)3*DD*DD];  // weights transposed [z][n][k] fp16 permuted
__device__ __half g_xh [(size_t)BSZ*DD];   // final-LN output fp16 permuted
__device__ __half g_Eh [(size_t)VV*DD];    // E fp16 permuted
__device__ int    g_prog[BB];              // completed segments per batch
__device__ int    g_tick;                  // worker ticket counter

// ================= helpers =================
__device__ __forceinline__ float warp_sum(float v) {
    #pragma unroll
    for (int o = 16; o; o >>= 1) v += __shfl_xor_sync(0xffffffffu, v, o);
    return v;
}
__device__ __forceinline__ uint32_t swz(uint32_t byte_off) {
    return byte_off ^ (((byte_off >> 7) & 3u) << 5);
}
__device__ __forceinline__ uint32_t smem_u32(const void* p) {
    uint32_t a;
    asm("{ .reg .u64 t; cvta.to.shared.u64 t, %1; cvt.u32.u64 %0, t; }" : "=r"(a) : "l"(p));
    return a;
}
__device__ __forceinline__ void cp16(uint32_t d, const void* s) {
    asm volatile("cp.async.cg.shared.global [%0], [%1], 16;" :: "r"(d), "l"(s) : "memory");
}
__device__ __forceinline__ void cpcommit() {
    asm volatile("cp.async.commit_group;" ::: "memory");
}
template<int N> __device__ __forceinline__ void cpwait() {
    asm volatile("cp.async.wait_group %0;" :: "n"(N) : "memory");
}
__device__ __forceinline__ void mma16816(float* c, const uint32_t* a, uint32_t b0, uint32_t b1) {
    asm volatile(
        "mma.sync.aligned.m16n8k16.row.col.f32.f16.f16.f32 "
        "{%0,%1,%2,%3}, {%4,%5,%6,%7}, {%8,%9}, {%0,%1,%2,%3};"
        : "+f"(c[0]), "+f"(c[1]), "+f"(c[2]), "+f"(c[3])
        : "r"(a[0]), "r"(a[1]), "r"(a[2]), "r"(a[3]), "r"(b0), "r"(b1));
}
__device__ __forceinline__ void pack_k16(const float* v, uint32_t* w) {
    #pragma unroll
    for (int j = 0; j < 8; j++) {
        int p = (j & 1) ? (4 + (j >> 1)) : (j >> 1);
        __half2 h = __floats2half2_rn(v[2*p], v[2*p+1]);
        w[j] = *(uint32_t*)&h;
    }
}
__device__ __forceinline__ void ldrow16(float* v, const float* p, int lane) {
    const float4* p4 = (const float4*)(p + lane * 16);
    #pragma unroll
    for (int i = 0; i < 4; i++) {
        float4 t = p4[i];
        v[i*4+0] = t.x; v[i*4+1] = t.y; v[i*4+2] = t.z; v[i*4+3] = t.w;
    }
}

// ---------------- 0a. E -> fp16 permuted ----------------
__global__ void k_conv_E(const float* __restrict__ E) {
    int idx = blockIdx.x * blockDim.x + threadIdx.x;
    int n = idx >> 5, blk = idx & 31;
    const float* src = E + (size_t)n * DD + blk * 16;
    float v[16];
    #pragma unroll
    for (int i = 0; i < 4; i++) {
        float4 t = *(const float4*)(src + i * 4);
        v[i*4+0] = t.x; v[i*4+1] = t.y; v[i*4+2] = t.z; v[i*4+3] = t.w;
    }
    uint32_t w[8];
    pack_k16(v, w);
    uint4* dst = (uint4*)((char*)g_Eh + ((size_t)n * DD + blk * 16) * 2);
    dst[0] = make_uint4(w[0], w[1], w[2], w[3]);
    dst[1] = make_uint4(w[4], w[5], w[6], w[7]);
}

// ---------------- 0b. W -> transposed fp16 permuted ----------------
__global__ void k_conv_W(const float* __restrict__ Wih, const float* __restrict__ W1,
                         const float* __restrict__ W2) {
    int t = blockIdx.x * blockDim.x + threadIdx.x;
    int z = t / (DD * 32);
    int rem = t % (DD * 32);
    int n = rem >> 5, blk = rem & 31;
    const float* W = (z == 0) ? Wih : (z == 1) ? W1 : W2;
    float v[16];
    #pragma unroll
    for (int kk = 0; kk < 16; kk++)
        v[kk] = W[(size_t)(blk * 16 + kk) * DD + n];
    uint32_t w[8];
    pack_k16(v, w);
    uint4* dst = (uint4*)((char*)g_Wh + (((size_t)z * DD + n) * DD + blk * 16) * 2);
    dst[0] = make_uint4(w[0], w[1], w[2], w[3]);
    dst[1] = make_uint4(w[4], w[5], w[6], w[7]);
}

// ---------------- 1. embedding gather -> fp16 permuted ----------------
__global__ void k_gather(const int* __restrict__ tokens, const float* __restrict__ E) {
    int row = blockIdx.x * 8 + (threadIdx.x >> 5);
    int lane = threadIdx.x & 31;
    int tok = tokens[row];
    const float* src = E + (size_t)tok * DD + lane * 16;
    float v[16];
    #pragma unroll
    for (int i = 0; i < 4; i++) {
        float4 t = *(const float4*)(src + i * 4);
        v[i*4+0] = t.x; v[i*4+1] = t.y; v[i*4+2] = t.z; v[i*4+3] = t.w;
    }
    uint32_t w[8];
    pack_k16(v, w);
    uint4* dst = (uint4*)((char*)g_embh + ((size_t)row * DD + lane * 16) * 2);
    dst[0] = make_uint4(w[0], w[1], w[2], w[3]);
    dst[1] = make_uint4(w[4], w[5], w[6], w[7]);
}

// ---------------- 2. phase-1 GEMMs via fp16 mma (fused 3x) ----------------
#define STAGE_BYTES 32768
#define SMEM_MMA (3*STAGE_BYTES)
#define NCHUNK 8

__global__ __launch_bounds__(256, 2) void k_p1_mma(
    const float* __restrict__ bh, const float* __restrict__ b1f,
    const float* __restrict__ b2f)
{
    extern __shared__ char smem[];
    const uint32_t sb = smem_u32(smem);
    const int tid = threadIdx.x;
    const int wid = tid >> 5, lane = tid & 31;
    const int g = lane >> 2, t = lane & 3;
    const int warpM = wid >> 2, warpN = wid & 3;
    const int m0 = blockIdx.y * 128;
    const int z = blockIdx.x >> 2;
    const int nloc0 = (blockIdx.x & 3) * 128;
    const float* bias = (z == 0) ? bh : (z == 1) ? b1f : b2f;
    float* Out = (z == 0) ? g_f : (z == 1) ? g_x : g_t;

    float acc[4][4][4];
    #pragma unroll
    for (int mt = 0; mt < 4; mt++)
        #pragma unroll
        for (int nt = 0; nt < 4; nt++)
            #pragma unroll
            for (int i = 0; i < 4; i++) acc[mt][nt][i] = 0.f;

    const char* gA = (const char*)g_embh + (size_t)m0 * DD * 2;
    const char* gB = (const char*)g_Wh + ((size_t)z * DD + nloc0) * DD * 2;

    auto LOAD = [&](int c) {
        uint32_t st = sb + (uint32_t)(c % 3) * STAGE_BYTES;
        int kb = c * 128;
        #pragma unroll
        for (int it = 0; it < 4; it++) {
            int idx = it * 256 + tid;
            int row = idx >> 3, q = idx & 7;
            uint32_t so = swz((uint32_t)(row * 128 + q * 16));
            cp16(st + so,         gA + (size_t)row * 1024 + kb + q * 16);
            cp16(st + 16384 + so, gB + (size_t)row * 1024 + kb + q * 16);
        }
        cpcommit();
    };
    auto COMP = [&](int buf) {
        const char* sA = smem + buf * STAGE_BYTES;
        const char* sB = smem + buf * STAGE_BYTES + 16384;
        #pragma unroll
        for (int kk = 0; kk < 4; kk++) {
            uint32_t a[4][4];
            #pragma unroll
            for (int mt = 0; mt < 4; mt++) {
                int r0 = warpM * 64 + mt * 16 + g;
                uint2 v1 = *(const uint2*)(sA + swz((uint32_t)(r0 * 128 + kk * 32 + t * 8)));
                uint2 v2 = *(const uint2*)(sA + swz((uint32_t)((r0 + 8) * 128 + kk * 32 + t * 8)));
                a[mt][0] = v1.x; a[mt][1] = v2.x; a[mt][2] = v1.y; a[mt][3] = v2.y;
            }
            #pragma unroll
            for (int nt = 0; nt < 4; nt++) {
                int nr = warpN * 32 + nt * 8 + g;
                uint2 bv = *(const uint2*)(sB + swz((uint32_t)(nr * 128 + kk * 32 + t * 8)));
                #pragma unroll
                for (int mt = 0; mt < 4; mt++)
                    mma16816(acc[mt][nt], a[mt], bv.x, bv.y);
            }
        }
    };

    LOAD(0); LOAD(1);
    #pragma unroll 1
    for (int c = 0; c < NCHUNK; c++) {
        if (c < NCHUNK - 1) cpwait<1>(); else cpwait<0>();
        __syncthreads();
        if (c + 2 < NCHUNK) LOAD(c + 2);
        COMP(c % 3);
    }

    #pragma unroll
    for (int mt = 0; mt < 4; mt++) {
        int mrow = m0 + warpM * 64 + mt * 16 + g;
        #pragma unroll
        for (int nt = 0; nt < 4; nt++) {
            int nl = nloc0 + warpN * 32 + nt * 8 + 2 * t;
            float bx = bias[nl], by = bias[nl + 1];
            float2 lo, hi;
            lo.x = acc[mt][nt][0] + bx; lo.y = acc[mt][nt][1] + by;
            hi.x = acc[mt][nt][2] + bx; hi.y = acc[mt][nt][3] + by;
            if (z == 0) {
                lo.x = 1.f/(1.f+expf(-lo.x)); lo.y = 1.f/(1.f+expf(-lo.y));
                hi.x = 1.f/(1.f+expf(-hi.x)); hi.y = 1.f/(1.f+expf(-hi.y));
            }
            *(float2*)(Out + (size_t)mrow * DD + nl) = lo;
            *(float2*)(Out + (size_t)(mrow + 8) * DD + nl) = hi;
        }
    }
}

// ---------------- 3. combine: x = silu(z1)*z2 ; also reset pipeline counters ----
__global__ void k_combine() {
    if (blockIdx.x == 0) {
        if (threadIdx.x < BB) g_prog[threadIdx.x] = 0;
        if (threadIdx.x == BB) g_tick = 0;
    }
    size_t i = (size_t)blockIdx.x * blockDim.x + threadIdx.x;
    float4 z1 = ((const float4*)g_x)[i];
    float4 z2 = ((const float4*)g_t)[i];
    float4 r;
    r.x = (z1.x / (1.f + expf(-z1.x))) * z2.x;
    r.y = (z1.y / (1.f + expf(-z1.y))) * z2.y;
    r.z = (z1.z / (1.f + expf(-z1.z))) * z2.z;
    r.w = (z1.w / (1.f + expf(-z1.w))) * z2.w;
    ((float4*)g_x)[i] = r;
}

// ---------------- 4. fused persistent kernel: scan+finln producers, logits workers ----
__global__ __launch_bounds__(256, 2) void k_fused(
    float* __restrict__ out,
    const float* __restrict__ h0,
    const float* __restrict__ lng, const float* __restrict__ lnb,
    const float* __restrict__ lnfg, const float* __restrict__ lnfb)
{
    extern __shared__ char smem[];
    const int tid = threadIdx.x;
    const int wid = tid >> 5, lane = tid & 31;

    if (blockIdx.x < BB) {
        // ================= scan CTA for batch b =================
        float* ring = (float*)smem;                         // 8 stages x 1024 floats
        volatile int* prog = (volatile int*)(smem + 32768); // [0]=scan steps, [1..7]=finln warp progress
        const int b = blockIdx.x;
        if (tid < 16) prog[tid] = 0;
        __syncthreads();

        if (wid == 0) {
            // ---- producer warp: the recurrence ----
            size_t base = (size_t)b * SS * DD;
            auto issue = [&](int s) {
                if (s < SS) {
                    uint32_t dst = smem_u32(ring + (size_t)(s & 7) * 1024);
                    const float* fs = g_f + base + (size_t)s * DD;
                    const float* xs = g_x + base + (size_t)s * DD;
                    #pragma unroll
                    for (int i = 0; i < 4; i++) {
                        int c = i * 32 + lane;
                        cp16(dst + c * 16,        fs + c * 4);
                        cp16(dst + 2048 + c * 16, xs + c * 4);
                    }
                }
                cpcommit();
            };
            #pragma unroll
            for (int p = 0; p < 6; p++) issue(p);

            float h[16], gw[16], gb[16];
            #pragma unroll
            for (int i = 0; i < 4; i++) {
                int off = i * 128 + lane * 4;
                *(float4*)(h  + i*4) = *(const float4*)(h0  + off);
                *(float4*)(gw + i*4) = *(const float4*)(lng + off);
                *(float4*)(gb + i*4) = *(const float4*)(lnb + off);
            }

            cpwait<5>();
            float fc[16], Bv[16];
            #pragma unroll
            for (int i = 0; i < 4; i++) {
                int off = i * 128 + lane * 4;
                float4 fv = *(const float4*)(ring + off);
                float4 xv = *(const float4*)(ring + 512 + off);
                fc[i*4+0]=fv.x; fc[i*4+1]=fv.y; fc[i*4+2]=fv.z; fc[i*4+3]=fv.w;
                Bv[i*4+0]=fmaf(-fv.x,xv.x,xv.x); Bv[i*4+1]=fmaf(-fv.y,xv.y,xv.y);
                Bv[i*4+2]=fmaf(-fv.z,xv.z,xv.z); Bv[i*4+3]=fmaf(-fv.w,xv.w,xv.w);
            }

            #pragma unroll 1
            for (int s = 0; s < SS; s++) {
                float hr[16];
                #pragma unroll
                for (int j = 0; j < 16; j++) hr[j] = fmaf(fc[j], h[j], Bv[j]);

                float p4s[4] = {0,0,0,0}, q4s[4] = {0,0,0,0};
                #pragma unroll
                for (int j = 0; j < 16; j++) {
                    p4s[j & 3] += hr[j];
                    q4s[j & 3] = fmaf(hr[j], hr[j], q4s[j & 3]);
                }
                float sum = (p4s[0] + p4s[1]) + (p4s[2] + p4s[3]);
                float ssq = (q4s[0] + q4s[1]) + (q4s[2] + q4s[3]);
                #pragma unroll
                for (int o = 16; o; o >>= 1) {
                    sum += __shfl_xor_sync(0xffffffffu, sum, o);
                    ssq += __shfl_xor_sync(0xffffffffu, ssq, o);
                }

                issue(s + 6);
                float hg[16];
                #pragma unroll
                for (int j = 0; j < 16; j++) hg[j] = hr[j] * gw[j];

                cpwait<5>();
                float fn[16], Bn[16];
                if (s + 1 < SS) {
                    const float* rg = ring + (size_t)((s + 1) & 7) * 1024;
                    #pragma unroll
                    for (int i = 0; i < 4; i++) {
                        int off = i * 128 + lane * 4;
                        float4 fv = *(const float4*)(rg + off);
                        float4 xv = *(const float4*)(rg + 512 + off);
                        fn[i*4+0]=fv.x; fn[i*4+1]=fv.y; fn[i*4+2]=fv.z; fn[i*4+3]=fv.w;
                        Bn[i*4+0]=fmaf(-fv.x,xv.x,xv.x); Bn[i*4+1]=fmaf(-fv.y,xv.y,xv.y);
                        Bn[i*4+2]=fmaf(-fv.z,xv.z,xv.z); Bn[i*4+3]=fmaf(-fv.w,xv.w,xv.w);
                    }
                }

                float mean = sum * (1.f / DD);
                float var  = fmaf(-mean, mean, ssq * (1.f / DD));
                float rstd = rsqrtf(var + EPSV);
                float t1   = mean * rstd;
                #pragma unroll
                for (int j = 0; j < 16; j++)
                    h[j] = fmaf(hg[j], rstd, fmaf(gw[j], -t1, gb[j] + h[j]));

                float* dst = g_xn + base + (size_t)s * DD;
                #pragma unroll
                for (int i = 0; i < 4; i++)
                    *(float4*)(dst + i * 128 + lane * 4) = *(float4*)(h + i * 4);

                if ((s & 7) == 7) {
                    __threadfence_block();
                    if (lane == 0) prog[0] = s + 1;
                }
                #pragma unroll
                for (int j = 0; j < 16; j++) { fc[j] = fn[j]; Bv[j] = Bn[j]; }
            }
        } else {
            // ---- trailing finln consumers: warps 1..7 ----
            float gwf[16], gbf[16];
            ldrow16(gwf, lnfg, lane);
            ldrow16(gbf, lnfb, lane);
            for (int r = wid - 1; r < SS; r += 7) {
                if (lane == 0) { while (prog[0] <= r) __nanosleep(40); }
                __syncwarp();
                __threadfence_block();
                const float* p = g_xn + ((size_t)b * SS + r) * DD;
                float v[16];
                ldrow16(v, p, lane);
                float s4[4] = {0,0,0,0}, q4[4] = {0,0,0,0};
                #pragma unroll
                for (int j = 0; j < 16; j++) {
                    s4[j & 3] += v[j];
                    q4[j & 3] = fmaf(v[j], v[j], q4[j & 3]);
                }
                float sum = warp_sum((s4[0] + s4[1]) + (s4[2] + s4[3]));
                float ssq = warp_sum((q4[0] + q4[1]) + (q4[2] + q4[3]));
                float mean = sum * (1.f / DD);
                float var  = ssq * (1.f / DD) - mean * mean;
                float rstd = rsqrtf(var + EPSV);
                #pragma unroll
                for (int j = 0; j < 16; j++)
                    v[j] = fmaf((v[j] - mean) * rstd, gwf[j], gbf[j]);
                uint32_t w[8];
                pack_k16(v, w);
                uint4* dst = (uint4*)((char*)g_xh + (((size_t)b * SS + r) * DD + lane * 16) * 2);
                dst[0] = make_uint4(w[0], w[1], w[2], w[3]);
                dst[1] = make_uint4(w[4], w[5], w[6], w[7]);
                __threadfence();
                if (lane == 0) {
                    prog[wid] = r + 1;
                    int m = prog[1];
                    #pragma unroll
                    for (int i = 2; i < 8; i++) { int pv = prog[i]; m = (pv < m) ? pv : m; }
                    int k = m >> 7;                     // SEGLEN=128
                    if (k > 0) atomicMax(&g_prog[b], k);
                }
                __syncwarp();
            }
            // ---- FIX (R7 deadlock): publish full completion after row loop ----
            __threadfence();
            if (lane == 0) {
                prog[wid] = SS;
                int m = prog[1];
                #pragma unroll
                for (int i = 2; i < 8; i++) { int pv = prog[i]; m = (pv < m) ? pv : m; }
                atomicMax(&g_prog[b], m >> 7);          // reaches NSEG when all warps done
            }
        }
        return;
    }

    // ================= persistent logits worker =================
    __shared__ int s_t;
    const uint32_t sb = smem_u32(smem);
    const int g = lane >> 2, t = lane & 3;
    const int warpM = wid >> 2, warpN = wid & 3;

    for (;;) {
        if (tid == 0) s_t = atomicAdd(&g_tick, 1);
        __syncthreads();
        int tkt = s_t;
        if (tkt >= NTILES) break;
        int seg = tkt / (NTILE_N * BB);
        int rem = tkt % (NTILE_N * BB);
        int b = rem & 7;
        int n0 = (rem >> 3) * 128;
        if (tid == 0) {
            int p;
            for (;;) {
                asm volatile("ld.global.acquire.gpu.s32 %0, [%1];" : "=r"(p) : "l"(&g_prog[b]));
                if (p > seg) break;
                __nanosleep(60);
            }
        }
        __syncthreads();
        const int m0 = b * SS + seg * SEGLEN;

        float acc[4][4][4];
        #pragma unroll
        for (int mt = 0; mt < 4; mt++)
            #pragma unroll
            for (int nt = 0; nt < 4; nt++)
                #pragma unroll
                for (int i = 0; i < 4; i++) acc[mt][nt][i] = 0.f;

        const char* gA = (const char*)g_xh + (size_t)m0 * DD * 2;
        const char* gB = (const char*)g_Eh + (size_t)n0 * DD * 2;

        auto LOAD = [&](int c) {
            uint32_t st = sb + (uint32_t)(c % 3) * STAGE_BYTES;
            int kb = c * 128;
            #pragma unroll
            for (int it = 0; it < 4; it++) {
                int idx = it * 256 + tid;
                int row = idx >> 3, q = idx & 7;
                uint32_t so = swz((uint32_t)(row * 128 + q * 16));
                cp16(st + so,         gA + (size_t)row * 1024 + kb + q * 16);
                cp16(st + 16384 + so, gB + (size_t)row * 1024 + kb + q * 16);
            }
            cpcommit();
        };
        auto COMP = [&](int buf) {
            const char* sA = smem + buf * STAGE_BYTES;
            const char* sB = smem + buf * STAGE_BYTES + 16384;
            #pragma unroll
            for (int kk = 0; kk < 4; kk++) {
                uint32_t a[4][4];
                #pragma unroll
                for (int mt = 0; mt < 4; mt++) {
                    int r0 = warpM * 64 + mt * 16 + g;
                    uint2 v1 = *(const uint2*)(sA + swz((uint32_t)(r0 * 128 + kk * 32 + t * 8)));
                    uint2 v2 = *(const uint2*)(sA + swz((uint32_t)((r0 + 8) * 128 + kk * 32 + t * 8)));
                    a[mt][0] = v1.x; a[mt][1] = v2.x; a[mt][2] = v1.y; a[mt][3] = v2.y;
                }
                #pragma unroll
                for (int nt = 0; nt < 4; nt++) {
                    int nr = warpN * 32 + nt * 8 + g;
                    uint2 bv = *(const uint2*)(sB + swz((uint32_t)(nr * 128 + kk * 32 + t * 8)));
                    #pragma unroll
                    for (int mt = 0; mt < 4; mt++)
                        mma16816(acc[mt][nt], a[mt], bv.x, bv.y);
                }
            }
        };

        LOAD(0); LOAD(1);
        #pragma unroll 1
        for (int c = 0; c < NCHUNK; c++) {
            if (c < NCHUNK - 1) cpwait<1>(); else cpwait<0>();
            __syncthreads();
            if (c + 2 < NCHUNK) LOAD(c + 2);
            COMP(c % 3);
        }

        #pragma unroll
        for (int mt = 0; mt < 4; mt++) {
            int mrow = m0 + warpM * 64 + mt * 16 + g;
            #pragma unroll
            for (int nt = 0; nt < 4; nt++) {
                int ncol = n0 + warpN * 32 + nt * 8 + 2 * t;
                float2 lo; lo.x = acc[mt][nt][0]; lo.y = acc[mt][nt][1];
                float2 hi; hi.x = acc[mt][nt][2]; hi.y = acc[mt][nt][3];
                *(float2*)(out + (size_t)mrow * VV + ncol) = lo;
                *(float2*)(out + (size_t)(mrow + 8) * VV + ncol) = hi;
            }
        }
        __syncthreads();   // protect smem stages + s_t before next iteration
    }
}

// ---------------- launch ----------------
extern "C" void kernel_launch(void* const* d_in, const int* in_sizes, int n_in,
                              void* d_out, int out_size) {
    const int*   tokens = (const int*)  d_in[0];
    const float* E      = (const float*)d_in[1];
    const float* W_ih   = (const float*)d_in[2];
    const float* b_h    = (const float*)d_in[3];
    const float* W1     = (const float*)d_in[4];
    const float* b1     = (const float*)d_in[5];
    const float* W2     = (const float*)d_in[6];
    const float* b2     = (const float*)d_in[7];
    const float* ln_g   = (const float*)d_in[8];
    const float* ln_b   = (const float*)d_in[9];
    const float* h0     = (const float*)d_in[10];
    const float* lnf_g  = (const float*)d_in[11];
    const float* lnf_b  = (const float*)d_in[12];
    float* out = (float*)d_out;

    static int init_done = 0;
    if (!init_done) {
        cudaFuncSetAttribute(k_p1_mma,  cudaFuncAttributeMaxDynamicSharedMemorySize, SMEM_MMA);
        cudaFuncSetAttribute(k_fused,   cudaFuncAttributeMaxDynamicSharedMemorySize, SMEM_MMA);
        init_done = 1;
    }

    k_conv_E<<<(VV*32)/256, 256>>>(E);
    k_conv_W<<<(3*DD*32)/256, 256>>>(W_ih, W1, W2);
    k_gather<<<BSZ/8, 256>>>(tokens, E);
    k_p1_mma<<<dim3(12, 64), 256, SMEM_MMA>>>(b_h, b1, b2);
    k_combine<<<4096, 256>>>();
    k_fused<<<BB + 288, 256, SMEM_MMA>>>(out, h0, ln_g, ln_b, lnf_g, lnf_b);
}

// round 9
// speedup vs baseline: 5.1281x; 1.0078x over previous
#include <cuda_runtime.h>
#include <cuda_fp16.h>
#include <math.h>
#include <stdint.h>

#define VV 32000
#define DD 512
#define BB 8
#define SS 1024
#define BSZ (BB*SS)          // 8192
#define EPSV 1e-5f
#define NSEG 8
#define SEGLEN (SS/NSEG)     // 128
#define NTILE_N 250
#define NTILES (NSEG*NTILE_N*BB)   // 16000

// ---------------- scratch (static device arrays; no cudaMalloc) ----------------
__device__ float  g_f  [(size_t)BSZ*DD];
__device__ float  g_x  [(size_t)BSZ*DD];
__device__ float  g_t  [(size_t)BSZ*DD];
__device__ float  g_xn [(size_t)BSZ*DD];
__device__ __half g_embh[(size_t)BSZ*DD];  // emb fp16 k16-pair-permuted
__device__ __half g_Wh [(size_t)3*DD*DD];  // weights transposed [z][n][k] fp16 permuted
__device__ __half g_xh [(size_t)BSZ*DD];   // final-LN output fp16 permuted
__device__ __half g_Eh [(size_t)VV*DD];    // E fp16 permuted
__device__ int    g_prog[BB];              // completed segments per batch
__device__ int    g_tick;                  // worker ticket counter
__device__ int    g_scansm[BB];            // smid of each scan CTA (-1 = unset)

// ================= helpers =================
__device__ __forceinline__ float warp_sum(float v) {
    #pragma unroll
    for (int o = 16; o; o >>= 1) v += __shfl_xor_sync(0xffffffffu, v, o);
    return v;
}
__device__ __forceinline__ uint32_t swz(uint32_t byte_off) {
    return byte_off ^ (((byte_off >> 7) & 3u) << 5);
}
__device__ __forceinline__ uint32_t smem_u32(const void* p) {
    uint32_t a;
    asm("{ .reg .u64 t; cvta.to.shared.u64 t, %1; cvt.u32.u64 %0, t; }" : "=r"(a) : "l"(p));
    return a;
}
__device__ __forceinline__ void cp16(uint32_t d, const void* s) {
    asm volatile("cp.async.cg.shared.global [%0], [%1], 16;" :: "r"(d), "l"(s) : "memory");
}
__device__ __forceinline__ void cpcommit() {
    asm volatile("cp.async.commit_group;" ::: "memory");
}
template<int N> __device__ __forceinline__ void cpwait() {
    asm volatile("cp.async.wait_group %0;" :: "n"(N) : "memory");
}
__device__ __forceinline__ void mma16816(float* c, const uint32_t* a, uint32_t b0, uint32_t b1) {
    asm volatile(
        "mma.sync.aligned.m16n8k16.row.col.f32.f16.f16.f32 "
        "{%0,%1,%2,%3}, {%4,%5,%6,%7}, {%8,%9}, {%0,%1,%2,%3};"
        : "+f"(c[0]), "+f"(c[1]), "+f"(c[2]), "+f"(c[3])
        : "r"(a[0]), "r"(a[1]), "r"(a[2]), "r"(a[3]), "r"(b0), "r"(b1));
}
__device__ __forceinline__ void pack_k16(const float* v, uint32_t* w) {
    #pragma unroll
    for (int j = 0; j < 8; j++) {
        int p = (j & 1) ? (4 + (j >> 1)) : (j >> 1);
        __half2 h = __floats2half2_rn(v[2*p], v[2*p+1]);
        w[j] = *(uint32_t*)&h;
    }
}
__device__ __forceinline__ void ldrow16(float* v, const float* p, int lane) {
    const float4* p4 = (const float4*)(p + lane * 16);
    #pragma unroll
    for (int i = 0; i < 4; i++) {
        float4 t = p4[i];
        v[i*4+0] = t.x; v[i*4+1] = t.y; v[i*4+2] = t.z; v[i*4+3] = t.w;
    }
}

// ---------------- 0a. E -> fp16 permuted ----------------
__global__ void k_conv_E(const float* __restrict__ E) {
    int idx = blockIdx.x * blockDim.x + threadIdx.x;
    int n = idx >> 5, blk = idx & 31;
    const float* src = E + (size_t)n * DD + blk * 16;
    float v[16];
    #pragma unroll
    for (int i = 0; i < 4; i++) {
        float4 t = *(const float4*)(src + i * 4);
        v[i*4+0] = t.x; v[i*4+1] = t.y; v[i*4+2] = t.z; v[i*4+3] = t.w;
    }
    uint32_t w[8];
    pack_k16(v, w);
    uint4* dst = (uint4*)((char*)g_Eh + ((size_t)n * DD + blk * 16) * 2);
    dst[0] = make_uint4(w[0], w[1], w[2], w[3]);
    dst[1] = make_uint4(w[4], w[5], w[6], w[7]);
}

// ---------------- 0b. W -> transposed fp16 permuted ----------------
__global__ void k_conv_W(const float* __restrict__ Wih, const float* __restrict__ W1,
                         const float* __restrict__ W2) {
    int t = blockIdx.x * blockDim.x + threadIdx.x;
    int z = t / (DD * 32);
    int rem = t % (DD * 32);
    int n = rem >> 5, blk = rem & 31;
    const float* W = (z == 0) ? Wih : (z == 1) ? W1 : W2;
    float v[16];
    #pragma unroll
    for (int kk = 0; kk < 16; kk++)
        v[kk] = W[(size_t)(blk * 16 + kk) * DD + n];
    uint32_t w[8];
    pack_k16(v, w);
    uint4* dst = (uint4*)((char*)g_Wh + (((size_t)z * DD + n) * DD + blk * 16) * 2);
    dst[0] = make_uint4(w[0], w[1], w[2], w[3]);
    dst[1] = make_uint4(w[4], w[5], w[6], w[7]);
}

// ---------------- 1. embedding gather -> fp16 permuted ----------------
__global__ void k_gather(const int* __restrict__ tokens, const float* __restrict__ E) {
    int row = blockIdx.x * 8 + (threadIdx.x >> 5);
    int lane = threadIdx.x & 31;
    int tok = tokens[row];
    const float* src = E + (size_t)tok * DD + lane * 16;
    float v[16];
    #pragma unroll
    for (int i = 0; i < 4; i++) {
        float4 t = *(const float4*)(src + i * 4);
        v[i*4+0] = t.x; v[i*4+1] = t.y; v[i*4+2] = t.z; v[i*4+3] = t.w;
    }
    uint32_t w[8];
    pack_k16(v, w);
    uint4* dst = (uint4*)((char*)g_embh + ((size_t)row * DD + lane * 16) * 2);
    dst[0] = make_uint4(w[0], w[1], w[2], w[3]);
    dst[1] = make_uint4(w[4], w[5], w[6], w[7]);
}

// ---------------- 2. phase-1 GEMMs via fp16 mma (fused 3x) ----------------
#define STAGE_BYTES 32768
#define SMEM_MMA (3*STAGE_BYTES)
#define NCHUNK 8

__global__ __launch_bounds__(256, 2) void k_p1_mma(
    const float* __restrict__ bh, const float* __restrict__ b1f,
    const float* __restrict__ b2f)
{
    extern __shared__ char smem[];
    const uint32_t sb = smem_u32(smem);
    const int tid = threadIdx.x;
    const int wid = tid >> 5, lane = tid & 31;
    const int g = lane >> 2, t = lane & 3;
    const int warpM = wid >> 2, warpN = wid & 3;
    const int m0 = blockIdx.y * 128;
    const int z = blockIdx.x >> 2;
    const int nloc0 = (blockIdx.x & 3) * 128;
    const float* bias = (z == 0) ? bh : (z == 1) ? b1f : b2f;
    float* Out = (z == 0) ? g_f : (z == 1) ? g_x : g_t;

    float acc[4][4][4];
    #pragma unroll
    for (int mt = 0; mt < 4; mt++)
        #pragma unroll
        for (int nt = 0; nt < 4; nt++)
            #pragma unroll
            for (int i = 0; i < 4; i++) acc[mt][nt][i] = 0.f;

    const char* gA = (const char*)g_embh + (size_t)m0 * DD * 2;
    const char* gB = (const char*)g_Wh + ((size_t)z * DD + nloc0) * DD * 2;

    auto LOAD = [&](int c) {
        uint32_t st = sb + (uint32_t)(c % 3) * STAGE_BYTES;
        int kb = c * 128;
        #pragma unroll
        for (int it = 0; it < 4; it++) {
            int idx = it * 256 + tid;
            int row = idx >> 3, q = idx & 7;
            uint32_t so = swz((uint32_t)(row * 128 + q * 16));
            cp16(st + so,         gA + (size_t)row * 1024 + kb + q * 16);
            cp16(st + 16384 + so, gB + (size_t)row * 1024 + kb + q * 16);
        }
        cpcommit();
    };
    auto COMP = [&](int buf) {
        const char* sA = smem + buf * STAGE_BYTES;
        const char* sB = smem + buf * STAGE_BYTES + 16384;
        #pragma unroll
        for (int kk = 0; kk < 4; kk++) {
            uint32_t a[4][4];
            #pragma unroll
            for (int mt = 0; mt < 4; mt++) {
                int r0 = warpM * 64 + mt * 16 + g;
                uint2 v1 = *(const uint2*)(sA + swz((uint32_t)(r0 * 128 + kk * 32 + t * 8)));
                uint2 v2 = *(const uint2*)(sA + swz((uint32_t)((r0 + 8) * 128 + kk * 32 + t * 8)));
                a[mt][0] = v1.x; a[mt][1] = v2.x; a[mt][2] = v1.y; a[mt][3] = v2.y;
            }
            #pragma unroll
            for (int nt = 0; nt < 4; nt++) {
                int nr = warpN * 32 + nt * 8 + g;
                uint2 bv = *(const uint2*)(sB + swz((uint32_t)(nr * 128 + kk * 32 + t * 8)));
                #pragma unroll
                for (int mt = 0; mt < 4; mt++)
                    mma16816(acc[mt][nt], a[mt], bv.x, bv.y);
            }
        }
    };

    LOAD(0); LOAD(1);
    #pragma unroll 1
    for (int c = 0; c < NCHUNK; c++) {
        if (c < NCHUNK - 1) cpwait<1>(); else cpwait<0>();
        __syncthreads();
        if (c + 2 < NCHUNK) LOAD(c + 2);
        COMP(c % 3);
    }

    #pragma unroll
    for (int mt = 0; mt < 4; mt++) {
        int mrow = m0 + warpM * 64 + mt * 16 + g;
        #pragma unroll
        for (int nt = 0; nt < 4; nt++) {
            int nl = nloc0 + warpN * 32 + nt * 8 + 2 * t;
            float bx = bias[nl], by = bias[nl + 1];
            float2 lo, hi;
            lo.x = acc[mt][nt][0] + bx; lo.y = acc[mt][nt][1] + by;
            hi.x = acc[mt][nt][2] + bx; hi.y = acc[mt][nt][3] + by;
            if (z == 0) {
                lo.x = 1.f/(1.f+expf(-lo.x)); lo.y = 1.f/(1.f+expf(-lo.y));
                hi.x = 1.f/(1.f+expf(-hi.x)); hi.y = 1.f/(1.f+expf(-hi.y));
            }
            *(float2*)(Out + (size_t)mrow * DD + nl) = lo;
            *(float2*)(Out + (size_t)(mrow + 8) * DD + nl) = hi;
        }
    }
}

// ---------------- 3. combine: x = silu(z1)*z2 ; also reset pipeline counters ----
__global__ void k_combine() {
    if (blockIdx.x == 0) {
        if (threadIdx.x < BB) { g_prog[threadIdx.x] = 0; g_scansm[threadIdx.x] = -1; }
        if (threadIdx.x == BB) g_tick = 0;
    }
    size_t i = (size_t)blockIdx.x * blockDim.x + threadIdx.x;
    float4 z1 = ((const float4*)g_x)[i];
    float4 z2 = ((const float4*)g_t)[i];
    float4 r;
    r.x = (z1.x / (1.f + expf(-z1.x))) * z2.x;
    r.y = (z1.y / (1.f + expf(-z1.y))) * z2.y;
    r.z = (z1.z / (1.f + expf(-z1.z))) * z2.z;
    r.w = (z1.w / (1.f + expf(-z1.w))) * z2.w;
    ((float4*)g_x)[i] = r;
}

// ---------------- 4. fused persistent kernel ----------------
// blocks 0..7: scan CTA (producer = warp 7 for hi-wid arbiter priority; finln = warps 0-6)
// other blocks: persistent logits workers; workers co-resident with a scan CTA exit.
__global__ __launch_bounds__(256, 2) void k_fused(
    float* __restrict__ out,
    const float* __restrict__ h0,
    const float* __restrict__ lng, const float* __restrict__ lnb,
    const float* __restrict__ lnfg, const float* __restrict__ lnfb)
{
    extern __shared__ char smem[];
    const int tid = threadIdx.x;
    const int wid = tid >> 5, lane = tid & 31;
    uint32_t mysm;
    asm("mov.u32 %0, %%smid;" : "=r"(mysm));

    if (blockIdx.x < BB) {
        // ================= scan CTA for batch b =================
        float* ring = (float*)smem;                         // 8 stages x 1024 floats
        volatile int* prog = (volatile int*)(smem + 32768); // [0]=scan steps, [1..7]=finln warps 0-6
        const int b = blockIdx.x;
        if (tid == 0) atomicExch(&g_scansm[b], (int)mysm);  // publish smid for worker eviction
        if (tid < 16) prog[tid] = 0;
        __syncthreads();

        if (wid == 7) {
            // ---- producer warp (highest wid = highest arbiter priority) ----
            size_t base = (size_t)b * SS * DD;
            auto issue = [&](int s) {
                if (s < SS) {
                    uint32_t dst = smem_u32(ring + (size_t)(s & 7) * 1024);
                    const float* fs = g_f + base + (size_t)s * DD;
                    const float* xs = g_x + base + (size_t)s * DD;
                    #pragma unroll
                    for (int i = 0; i < 4; i++) {
                        int c = i * 32 + lane;
                        cp16(dst + c * 16,        fs + c * 4);
                        cp16(dst + 2048 + c * 16, xs + c * 4);
                    }
                }
                cpcommit();
            };
            #pragma unroll
            for (int p = 0; p < 6; p++) issue(p);

            float h[16], gw[16], gb[16];
            #pragma unroll
            for (int i = 0; i < 4; i++) {
                int off = i * 128 + lane * 4;
                *(float4*)(h  + i*4) = *(const float4*)(h0  + off);
                *(float4*)(gw + i*4) = *(const float4*)(lng + off);
                *(float4*)(gb + i*4) = *(const float4*)(lnb + off);
            }

            cpwait<5>();
            float fc[16], Bv[16];
            #pragma unroll
            for (int i = 0; i < 4; i++) {
                int off = i * 128 + lane * 4;
                float4 fv = *(const float4*)(ring + off);
                float4 xv = *(const float4*)(ring + 512 + off);
                fc[i*4+0]=fv.x; fc[i*4+1]=fv.y; fc[i*4+2]=fv.z; fc[i*4+3]=fv.w;
                Bv[i*4+0]=fmaf(-fv.x,xv.x,xv.x); Bv[i*4+1]=fmaf(-fv.y,xv.y,xv.y);
                Bv[i*4+2]=fmaf(-fv.z,xv.z,xv.z); Bv[i*4+3]=fmaf(-fv.w,xv.w,xv.w);
            }

            #pragma unroll 1
            for (int s = 0; s < SS; s++) {
                float hr[16];
                #pragma unroll
                for (int j = 0; j < 16; j++) hr[j] = fmaf(fc[j], h[j], Bv[j]);

                float p4s[4] = {0,0,0,0}, q4s[4] = {0,0,0,0};
                #pragma unroll
                for (int j = 0; j < 16; j++) {
                    p4s[j & 3] += hr[j];
                    q4s[j & 3] = fmaf(hr[j], hr[j], q4s[j & 3]);
                }
                float sum = (p4s[0] + p4s[1]) + (p4s[2] + p4s[3]);
                float ssq = (q4s[0] + q4s[1]) + (q4s[2] + q4s[3]);
                #pragma unroll
                for (int o = 16; o; o >>= 1) {
                    sum += __shfl_xor_sync(0xffffffffu, sum, o);
                    ssq += __shfl_xor_sync(0xffffffffu, ssq, o);
                }

                issue(s + 6);
                float hg[16];
                #pragma unroll
                for (int j = 0; j < 16; j++) hg[j] = hr[j] * gw[j];

                cpwait<5>();
                float fn[16], Bn[16];
                if (s + 1 < SS) {
                    const float* rg = ring + (size_t)((s + 1) & 7) * 1024;
                    #pragma unroll
                    for (int i = 0; i < 4; i++) {
                        int off = i * 128 + lane * 4;
                        float4 fv = *(const float4*)(rg + off);
                        float4 xv = *(const float4*)(rg + 512 + off);
                        fn[i*4+0]=fv.x; fn[i*4+1]=fv.y; fn[i*4+2]=fv.z; fn[i*4+3]=fv.w;
                        Bn[i*4+0]=fmaf(-fv.x,xv.x,xv.x); Bn[i*4+1]=fmaf(-fv.y,xv.y,xv.y);
                        Bn[i*4+2]=fmaf(-fv.z,xv.z,xv.z); Bn[i*4+3]=fmaf(-fv.w,xv.w,xv.w);
                    }
                }

                float mean = sum * (1.f / DD);
                float var  = fmaf(-mean, mean, ssq * (1.f / DD));
                float rstd = rsqrtf(var + EPSV);
                float t1   = mean * rstd;
                #pragma unroll
                for (int j = 0; j < 16; j++)
                    h[j] = fmaf(hg[j], rstd, fmaf(gw[j], -t1, gb[j] + h[j]));

                float* dst = g_xn + base + (size_t)s * DD;
                #pragma unroll
                for (int i = 0; i < 4; i++)
                    *(float4*)(dst + i * 128 + lane * 4) = *(float4*)(h + i * 4);

                if ((s & 7) == 7) {
                    __threadfence_block();
                    if (lane == 0) prog[0] = s + 1;
                }
                #pragma unroll
                for (int j = 0; j < 16; j++) { fc[j] = fn[j]; Bv[j] = Bn[j]; }
            }
        } else {
            // ---- trailing finln consumers: warps 0..6, rows r = wid + 7k ----
            float gwf[16], gbf[16];
            ldrow16(gwf, lnfg, lane);
            ldrow16(gbf, lnfb, lane);
            const int slot = wid + 1;
            for (int r = wid; r < SS; r += 7) {
                if (lane == 0) { while (prog[0] <= r) __nanosleep(40); }
                __syncwarp();
                __threadfence_block();
                const float* p = g_xn + ((size_t)b * SS + r) * DD;
                float v[16];
                ldrow16(v, p, lane);
                float s4[4] = {0,0,0,0}, q4[4] = {0,0,0,0};
                #pragma unroll
                for (int j = 0; j < 16; j++) {
                    s4[j & 3] += v[j];
                    q4[j & 3] = fmaf(v[j], v[j], q4[j & 3]);
                }
                float sum = warp_sum((s4[0] + s4[1]) + (s4[2] + s4[3]));
                float ssq = warp_sum((q4[0] + q4[1]) + (q4[2] + q4[3]));
                float mean = sum * (1.f / DD);
                float var  = ssq * (1.f / DD) - mean * mean;
                float rstd = rsqrtf(var + EPSV);
                #pragma unroll
                for (int j = 0; j < 16; j++)
                    v[j] = fmaf((v[j] - mean) * rstd, gwf[j], gbf[j]);
                uint32_t w[8];
                pack_k16(v, w);
                uint4* dst = (uint4*)((char*)g_xh + (((size_t)b * SS + r) * DD + lane * 16) * 2);
                dst[0] = make_uint4(w[0], w[1], w[2], w[3]);
                dst[1] = make_uint4(w[4], w[5], w[6], w[7]);
                __threadfence();
                if (lane == 0) {
                    prog[slot] = r + 1;
                    int m = prog[1];
                    #pragma unroll
                    for (int i = 2; i < 8; i++) { int pv = prog[i]; m = (pv < m) ? pv : m; }
                    int k = m >> 7;                     // SEGLEN=128
                    if (k > 0) atomicMax(&g_prog[b], k);
                }
                __syncwarp();
            }
            // publish full completion (termination fix)
            __threadfence();
            if (lane == 0) {
                prog[slot] = SS;
                int m = prog[1];
                #pragma unroll
                for (int i = 2; i < 8; i++) { int pv = prog[i]; m = (pv < m) ? pv : m; }
                atomicMax(&g_prog[b], m >> 7);
            }
        }
        return;
    }

    // ================= persistent logits worker =================
    __shared__ int s_t;
    __shared__ int s_evict;
    // eviction: wait for all scan CTAs to publish smids (same wave), exit if co-resident
    if (tid == 0) {
        int ev = 0;
        #pragma unroll 1
        for (int i = 0; i < BB; i++) {
            int v;
            do { v = atomicAdd(&g_scansm[i], 0); if (v < 0) __nanosleep(20); } while (v < 0);
            if ((uint32_t)v == mysm) ev = 1;
        }
        s_evict = ev;
    }
    __syncthreads();
    if (s_evict) return;

    const uint32_t sb = smem_u32(smem);
    const int g = lane >> 2, t = lane & 3;
    const int warpM = wid >> 2, warpN = wid & 3;

    for (;;) {
        if (tid == 0) s_t = atomicAdd(&g_tick, 1);
        __syncthreads();
        int tkt = s_t;
        if (tkt >= NTILES) break;
        int seg = tkt / (NTILE_N * BB);
        int rem = tkt % (NTILE_N * BB);
        int b = rem & 7;
        int n0 = (rem >> 3) * 128;
        if (tid == 0) {
            int p;
            for (;;) {
                asm volatile("ld.global.acquire.gpu.s32 %0, [%1];" : "=r"(p) : "l"(&g_prog[b]));
                if (p > seg) break;
                __nanosleep(60);
            }
        }
        __syncthreads();
        const int m0 = b * SS + seg * SEGLEN;

        float acc[4][4][4];
        #pragma unroll
        for (int mt = 0; mt < 4; mt++)
            #pragma unroll
            for (int nt = 0; nt < 4; nt++)
                #pragma unroll
                for (int i = 0; i < 4; i++) acc[mt][nt][i] = 0.f;

        const char* gA = (const char*)g_xh + (size_t)m0 * DD * 2;
        const char* gB = (const char*)g_Eh + (size_t)n0 * DD * 2;

        auto LOAD = [&](int c) {
            uint32_t st = sb + (uint32_t)(c % 3) * STAGE_BYTES;
            int kb = c * 128;
            #pragma unroll
            for (int it = 0; it < 4; it++) {
                int idx = it * 256 + tid;
                int row = idx >> 3, q = idx & 7;
                uint32_t so = swz((uint32_t)(row * 128 + q * 16));
                cp16(st + so,         gA + (size_t)row * 1024 + kb + q * 16);
                cp16(st + 16384 + so, gB + (size_t)row * 1024 + kb + q * 16);
            }
            cpcommit();
        };
        auto COMP = [&](int buf) {
            const char* sA = smem + buf * STAGE_BYTES;
            const char* sB = smem + buf * STAGE_BYTES + 16384;
            #pragma unroll
            for (int kk = 0; kk < 4; kk++) {
                uint32_t a[4][4];
                #pragma unroll
                for (int mt = 0; mt < 4; mt++) {
                    int r0 = warpM * 64 + mt * 16 + g;
                    uint2 v1 = *(const uint2*)(sA + swz((uint32_t)(r0 * 128 + kk * 32 + t * 8)));
                    uint2 v2 = *(const uint2*)(sA + swz((uint32_t)((r0 + 8) * 128 + kk * 32 + t * 8)));
                    a[mt][0] = v1.x; a[mt][1] = v2.x; a[mt][2] = v1.y; a[mt][3] = v2.y;
                }
                #pragma unroll
                for (int nt = 0; nt < 4; nt++) {
                    int nr = warpN * 32 + nt * 8 + g;
                    uint2 bv = *(const uint2*)(sB + swz((uint32_t)(nr * 128 + kk * 32 + t * 8)));
                    #pragma unroll
                    for (int mt = 0; mt < 4; mt++)
                        mma16816(acc[mt][nt], a[mt], bv.x, bv.y);
                }
            }
        };

        LOAD(0); LOAD(1);
        #pragma unroll 1
        for (int c = 0; c < NCHUNK; c++) {
            if (c < NCHUNK - 1) cpwait<1>(); else cpwait<0>();
            __syncthreads();
            if (c + 2 < NCHUNK) LOAD(c + 2);
            COMP(c % 3);
        }

        #pragma unroll
        for (int mt = 0; mt < 4; mt++) {
            int mrow = m0 + warpM * 64 + mt * 16 + g;
            #pragma unroll
            for (int nt = 0; nt < 4; nt++) {
                int ncol = n0 + warpN * 32 + nt * 8 + 2 * t;
                float2 lo; lo.x = acc[mt][nt][0]; lo.y = acc[mt][nt][1];
                float2 hi; hi.x = acc[mt][nt][2]; hi.y = acc[mt][nt][3];
                *(float2*)(out + (size_t)mrow * VV + ncol) = lo;
                *(float2*)(out + (size_t)(mrow + 8) * VV + ncol) = hi;
            }
        }
        __syncthreads();   // protect smem stages + s_t before next iteration
    }
}

// ---------------- launch ----------------
extern "C" void kernel_launch(void* const* d_in, const int* in_sizes, int n_in,
                              void* d_out, int out_size) {
    const int*   tokens = (const int*)  d_in[0];
    const float* E      = (const float*)d_in[1];
    const float* W_ih   = (const float*)d_in[2];
    const float* b_h    = (const float*)d_in[3];
    const float* W1     = (const float*)d_in[4];
    const float* b1     = (const float*)d_in[5];
    const float* W2     = (const float*)d_in[6];
    const float* b2     = (const float*)d_in[7];
    const float* ln_g   = (const float*)d_in[8];
    const float* ln_b   = (const float*)d_in[9];
    const float* h0     = (const float*)d_in[10];
    const float* lnf_g  = (const float*)d_in[11];
    const float* lnf_b  = (const float*)d_in[12];
    float* out = (float*)d_out;

    static int init_done = 0;
    if (!init_done) {
        cudaFuncSetAttribute(k_p1_mma,  cudaFuncAttributeMaxDynamicSharedMemorySize, SMEM_MMA);
        cudaFuncSetAttribute(k_fused,   cudaFuncAttributeMaxDynamicSharedMemorySize, SMEM_MMA);
        init_done = 1;
    }

    k_conv_E<<<(VV*32)/256, 256>>>(E);
    k_conv_W<<<(3*DD*32)/256, 256>>>(W_ih, W1, W2);
    k_gather<<<BSZ/8, 256>>>(tokens, E);
    k_p1_mma<<<dim3(12, 64), 256, SMEM_MMA>>>(b_h, b1, b2);
    k_combine<<<4096, 256>>>();
    k_fused<<<BB + 288, 256, SMEM_MMA>>>(out, h0, ln_g, ln_b, lnf_g, lnf_b);
}

// round 10
// speedup vs baseline: 5.1481x; 1.0039x over previous
#include <cuda_runtime.h>
#include <cuda_fp16.h>
#include <math.h>
#include <stdint.h>

#define VV 32000
#define DD 512
#define BB 8
#define SS 1024
#define BSZ (BB*SS)          // 8192
#define EPSV 1e-5f
#define NSEG 8
#define SEGLEN (SS/NSEG)     // 128
#define NTILE_N 250
#define NTILES (NSEG*NTILE_N*BB)   // 16000

// ---------------- scratch (static device arrays; no cudaMalloc) ----------------
__device__ float  g_f  [(size_t)BSZ*DD];
__device__ float  g_x  [(size_t)BSZ*DD];
__device__ float  g_t  [(size_t)BSZ*DD];
__device__ float  g_xn [(size_t)BSZ*DD];
__device__ __half g_embh[(size_t)BSZ*DD];  // emb fp16 k16-pair-permuted
__device__ __half g_Wh [(size_t)3*DD*DD];  // weights transposed [z][n][k] fp16 permuted
__device__ __half g_xh [(size_t)BSZ*DD];   // final-LN output fp16 permuted
__device__ __half g_Eh [(size_t)VV*DD];    // E fp16 permuted
__device__ int    g_prog[BB];              // completed segments per batch
__device__ int    g_tick;                  // worker ticket counter
__device__ int    g_scansm[BB];            // smid of each scan CTA (-1 = unset)

// ================= helpers =================
__device__ __forceinline__ float warp_sum(float v) {
    #pragma unroll
    for (int o = 16; o; o >>= 1) v += __shfl_xor_sync(0xffffffffu, v, o);
    return v;
}
__device__ __forceinline__ uint32_t swz(uint32_t byte_off) {
    return byte_off ^ (((byte_off >> 7) & 3u) << 5);
}
__device__ __forceinline__ uint32_t smem_u32(const void* p) {
    uint32_t a;
    asm("{ .reg .u64 t; cvta.to.shared.u64 t, %1; cvt.u32.u64 %0, t; }" : "=r"(a) : "l"(p));
    return a;
}
__device__ __forceinline__ void cp16(uint32_t d, const void* s) {
    asm volatile("cp.async.cg.shared.global [%0], [%1], 16;" :: "r"(d), "l"(s) : "memory");
}
__device__ __forceinline__ void cpcommit() {
    asm volatile("cp.async.commit_group;" ::: "memory");
}
template<int N> __device__ __forceinline__ void cpwait() {
    asm volatile("cp.async.wait_group %0;" :: "n"(N) : "memory");
}
__device__ __forceinline__ void mma16816(float* c, const uint32_t* a, uint32_t b0, uint32_t b1) {
    asm volatile(
        "mma.sync.aligned.m16n8k16.row.col.f32.f16.f16.f32 "
        "{%0,%1,%2,%3}, {%4,%5,%6,%7}, {%8,%9}, {%0,%1,%2,%3};"
        : "+f"(c[0]), "+f"(c[1]), "+f"(c[2]), "+f"(c[3])
        : "r"(a[0]), "r"(a[1]), "r"(a[2]), "r"(a[3]), "r"(b0), "r"(b1));
}
__device__ __forceinline__ void pack_k16(const float* v, uint32_t* w) {
    #pragma unroll
    for (int j = 0; j < 8; j++) {
        int p = (j & 1) ? (4 + (j >> 1)) : (j >> 1);
        __half2 h = __floats2half2_rn(v[2*p], v[2*p+1]);
        w[j] = *(uint32_t*)&h;
    }
}
__device__ __forceinline__ void ldrow16(float* v, const float* p, int lane) {
    const float4* p4 = (const float4*)(p + lane * 16);
    #pragma unroll
    for (int i = 0; i < 4; i++) {
        float4 t = p4[i];
        v[i*4+0] = t.x; v[i*4+1] = t.y; v[i*4+2] = t.z; v[i*4+3] = t.w;
    }
}

// ---------------- 0a. E -> fp16 permuted ----------------
__global__ void k_conv_E(const float* __restrict__ E) {
    int idx = blockIdx.x * blockDim.x + threadIdx.x;
    int n = idx >> 5, blk = idx & 31;
    const float* src = E + (size_t)n * DD + blk * 16;
    float v[16];
    #pragma unroll
    for (int i = 0; i < 4; i++) {
        float4 t = *(const float4*)(src + i * 4);
        v[i*4+0] = t.x; v[i*4+1] = t.y; v[i*4+2] = t.z; v[i*4+3] = t.w;
    }
    uint32_t w[8];
    pack_k16(v, w);
    uint4* dst = (uint4*)((char*)g_Eh + ((size_t)n * DD + blk * 16) * 2);
    dst[0] = make_uint4(w[0], w[1], w[2], w[3]);
    dst[1] = make_uint4(w[4], w[5], w[6], w[7]);
}

// ---------------- 0b. W -> transposed fp16 permuted ----------------
__global__ void k_conv_W(const float* __restrict__ Wih, const float* __restrict__ W1,
                         const float* __restrict__ W2) {
    int t = blockIdx.x * blockDim.x + threadIdx.x;
    int z = t / (DD * 32);
    int rem = t % (DD * 32);
    int n = rem >> 5, blk = rem & 31;
    const float* W = (z == 0) ? Wih : (z == 1) ? W1 : W2;
    float v[16];
    #pragma unroll
    for (int kk = 0; kk < 16; kk++)
        v[kk] = W[(size_t)(blk * 16 + kk) * DD + n];
    uint32_t w[8];
    pack_k16(v, w);
    uint4* dst = (uint4*)((char*)g_Wh + (((size_t)z * DD + n) * DD + blk * 16) * 2);
    dst[0] = make_uint4(w[0], w[1], w[2], w[3]);
    dst[1] = make_uint4(w[4], w[5], w[6], w[7]);
}

// ---------------- 1. embedding gather -> fp16 permuted ----------------
__global__ void k_gather(const int* __restrict__ tokens, const float* __restrict__ E) {
    int row = blockIdx.x * 8 + (threadIdx.x >> 5);
    int lane = threadIdx.x & 31;
    int tok = tokens[row];
    const float* src = E + (size_t)tok * DD + lane * 16;
    float v[16];
    #pragma unroll
    for (int i = 0; i < 4; i++) {
        float4 t = *(const float4*)(src + i * 4);
        v[i*4+0] = t.x; v[i*4+1] = t.y; v[i*4+2] = t.z; v[i*4+3] = t.w;
    }
    uint32_t w[8];
    pack_k16(v, w);
    uint4* dst = (uint4*)((char*)g_embh + ((size_t)row * DD + lane * 16) * 2);
    dst[0] = make_uint4(w[0], w[1], w[2], w[3]);
    dst[1] = make_uint4(w[4], w[5], w[6], w[7]);
}

// ---------------- 2. phase-1 GEMMs via fp16 mma (fused 3x) ----------------
#define STAGE_BYTES 32768
#define SMEM_MMA (3*STAGE_BYTES)
#define NCHUNK 8

__global__ __launch_bounds__(256, 2) void k_p1_mma(
    const float* __restrict__ bh, const float* __restrict__ b1f,
    const float* __restrict__ b2f)
{
    extern __shared__ char smem[];
    const uint32_t sb = smem_u32(smem);
    const int tid = threadIdx.x;
    const int wid = tid >> 5, lane = tid & 31;
    const int g = lane >> 2, t = lane & 3;
    const int warpM = wid >> 2, warpN = wid & 3;
    const int m0 = blockIdx.y * 128;
    const int z = blockIdx.x >> 2;
    const int nloc0 = (blockIdx.x & 3) * 128;
    const float* bias = (z == 0) ? bh : (z == 1) ? b1f : b2f;
    float* Out = (z == 0) ? g_f : (z == 1) ? g_x : g_t;

    float acc[4][4][4];
    #pragma unroll
    for (int mt = 0; mt < 4; mt++)
        #pragma unroll
        for (int nt = 0; nt < 4; nt++)
            #pragma unroll
            for (int i = 0; i < 4; i++) acc[mt][nt][i] = 0.f;

    const char* gA = (const char*)g_embh + (size_t)m0 * DD * 2;
    const char* gB = (const char*)g_Wh + ((size_t)z * DD + nloc0) * DD * 2;

    auto LOAD = [&](int c) {
        uint32_t st = sb + (uint32_t)(c % 3) * STAGE_BYTES;
        int kb = c * 128;
        #pragma unroll
        for (int it = 0; it < 4; it++) {
            int idx = it * 256 + tid;
            int row = idx >> 3, q = idx & 7;
            uint32_t so = swz((uint32_t)(row * 128 + q * 16));
            cp16(st + so,         gA + (size_t)row * 1024 + kb + q * 16);
            cp16(st + 16384 + so, gB + (size_t)row * 1024 + kb + q * 16);
        }
        cpcommit();
    };
    auto COMP = [&](int buf) {
        const char* sA = smem + buf * STAGE_BYTES;
        const char* sB = smem + buf * STAGE_BYTES + 16384;
        #pragma unroll
        for (int kk = 0; kk < 4; kk++) {
            uint32_t a[4][4];
            #pragma unroll
            for (int mt = 0; mt < 4; mt++) {
                int r0 = warpM * 64 + mt * 16 + g;
                uint2 v1 = *(const uint2*)(sA + swz((uint32_t)(r0 * 128 + kk * 32 + t * 8)));
                uint2 v2 = *(const uint2*)(sA + swz((uint32_t)((r0 + 8) * 128 + kk * 32 + t * 8)));
                a[mt][0] = v1.x; a[mt][1] = v2.x; a[mt][2] = v1.y; a[mt][3] = v2.y;
            }
            #pragma unroll
            for (int nt = 0; nt < 4; nt++) {
                int nr = warpN * 32 + nt * 8 + g;
                uint2 bv = *(const uint2*)(sB + swz((uint32_t)(nr * 128 + kk * 32 + t * 8)));
                #pragma unroll
                for (int mt = 0; mt < 4; mt++)
                    mma16816(acc[mt][nt], a[mt], bv.x, bv.y);
            }
        }
    };

    LOAD(0); LOAD(1);
    #pragma unroll 1
    for (int c = 0; c < NCHUNK; c++) {
        if (c < NCHUNK - 1) cpwait<1>(); else cpwait<0>();
        __syncthreads();
        if (c + 2 < NCHUNK) LOAD(c + 2);
        COMP(c % 3);
    }

    #pragma unroll
    for (int mt = 0; mt < 4; mt++) {
        int mrow = m0 + warpM * 64 + mt * 16 + g;
        #pragma unroll
        for (int nt = 0; nt < 4; nt++) {
            int nl = nloc0 + warpN * 32 + nt * 8 + 2 * t;
            float bx = bias[nl], by = bias[nl + 1];
            float2 lo, hi;
            lo.x = acc[mt][nt][0] + bx; lo.y = acc[mt][nt][1] + by;
            hi.x = acc[mt][nt][2] + bx; hi.y = acc[mt][nt][3] + by;
            if (z == 0) {
                lo.x = 1.f/(1.f+expf(-lo.x)); lo.y = 1.f/(1.f+expf(-lo.y));
                hi.x = 1.f/(1.f+expf(-hi.x)); hi.y = 1.f/(1.f+expf(-hi.y));
            }
            *(float2*)(Out + (size_t)mrow * DD + nl) = lo;
            *(float2*)(Out + (size_t)(mrow + 8) * DD + nl) = hi;
        }
    }
}

// ---------------- 3. combine: x = silu(z1)*z2 ; also reset pipeline counters ----
__global__ void k_combine() {
    if (blockIdx.x == 0) {
        if (threadIdx.x < BB) { g_prog[threadIdx.x] = 0; g_scansm[threadIdx.x] = -1; }
        if (threadIdx.x == BB) g_tick = 0;
    }
    size_t i = (size_t)blockIdx.x * blockDim.x + threadIdx.x;
    float4 z1 = ((const float4*)g_x)[i];
    float4 z2 = ((const float4*)g_t)[i];
    float4 r;
    r.x = (z1.x / (1.f + expf(-z1.x))) * z2.x;
    r.y = (z1.y / (1.f + expf(-z1.y))) * z2.y;
    r.z = (z1.z / (1.f + expf(-z1.z))) * z2.z;
    r.w = (z1.w / (1.f + expf(-z1.w))) * z2.w;
    ((float4*)g_x)[i] = r;
}

// ---------------- 4. fused persistent kernel ----------------
// blocks 0..7: scan CTA (producer = warp 7; finln = warps 0-6); others: logits workers.
// Producer register budget trimmed to fit the 128-reg cap without spills:
// peak live = h,gw,gb,hr,fc,Bv = 96 floats (fn/Bn/hg/e buffers eliminated).
__global__ __launch_bounds__(256, 2) void k_fused(
    float* __restrict__ out,
    const float* __restrict__ h0,
    const float* __restrict__ lng, const float* __restrict__ lnb,
    const float* __restrict__ lnfg, const float* __restrict__ lnfb)
{
    extern __shared__ char smem[];
    const int tid = threadIdx.x;
    const int wid = tid >> 5, lane = tid & 31;
    uint32_t mysm;
    asm("mov.u32 %0, %%smid;" : "=r"(mysm));

    if (blockIdx.x < BB) {
        // ================= scan CTA for batch b =================
        float* ring = (float*)smem;                         // 8 stages x 1024 floats
        volatile int* prog = (volatile int*)(smem + 32768); // [0]=scan steps, [1..7]=finln warps 0-6
        const int b = blockIdx.x;
        if (tid == 0) atomicExch(&g_scansm[b], (int)mysm);
        if (tid < 16) prog[tid] = 0;
        __syncthreads();

        if (wid == 7) {
            // ---- producer warp (highest wid = highest arbiter priority) ----
            size_t base = (size_t)b * SS * DD;
            auto issue = [&](int s) {
                if (s < SS) {
                    uint32_t dst = smem_u32(ring + (size_t)(s & 7) * 1024);
                    const float* fs = g_f + base + (size_t)s * DD;
                    const float* xs = g_x + base + (size_t)s * DD;
                    #pragma unroll
                    for (int i = 0; i < 4; i++) {
                        int c = i * 32 + lane;
                        cp16(dst + c * 16,        fs + c * 4);
                        cp16(dst + 2048 + c * 16, xs + c * 4);
                    }
                }
                cpcommit();
            };
            #pragma unroll
            for (int p = 0; p < 6; p++) issue(p);

            float h[16], gw[16], gb[16];
            #pragma unroll
            for (int i = 0; i < 4; i++) {
                int off = i * 128 + lane * 4;
                *(float4*)(h  + i*4) = *(const float4*)(h0  + off);
                *(float4*)(gw + i*4) = *(const float4*)(lng + off);
                *(float4*)(gb + i*4) = *(const float4*)(lnb + off);
            }

            cpwait<5>();
            float fc[16], Bv[16];
            #pragma unroll
            for (int i = 0; i < 4; i++) {
                int off = i * 128 + lane * 4;
                float4 fv = *(const float4*)(ring + off);
                float4 xv = *(const float4*)(ring + 512 + off);
                fc[i*4+0]=fv.x; fc[i*4+1]=fv.y; fc[i*4+2]=fv.z; fc[i*4+3]=fv.w;
                Bv[i*4+0]=fmaf(-fv.x,xv.x,xv.x); Bv[i*4+1]=fmaf(-fv.y,xv.y,xv.y);
                Bv[i*4+2]=fmaf(-fv.z,xv.z,xv.z); Bv[i*4+3]=fmaf(-fv.w,xv.w,xv.w);
            }

            #pragma unroll 1
            for (int s = 0; s < SS; s++) {
                float hr[16];
                #pragma unroll
                for (int j = 0; j < 16; j++) hr[j] = fmaf(fc[j], h[j], Bv[j]);
                // fc,Bv are DEAD here -> reloaded below for s+1 (no extra buffers)

                float p4s[4] = {0,0,0,0}, q4s[4] = {0,0,0,0};
                #pragma unroll
                for (int j = 0; j < 16; j++) {
                    p4s[j & 3] += hr[j];
                    q4s[j & 3] = fmaf(hr[j], hr[j], q4s[j & 3]);
                }
                float sum = (p4s[0] + p4s[1]) + (p4s[2] + p4s[3]);
                float ssq = (q4s[0] + q4s[1]) + (q4s[2] + q4s[3]);
                #pragma unroll
                for (int o = 16; o; o >>= 1) {
                    sum += __shfl_xor_sync(0xffffffffu, sum, o);
                    ssq += __shfl_xor_sync(0xffffffffu, ssq, o);
                }

                issue(s + 6);
                cpwait<5>();
                if (s + 1 < SS) {
                    const float* rg = ring + (size_t)((s + 1) & 7) * 1024;
                    #pragma unroll
                    for (int i = 0; i < 4; i++) {
                        int off = i * 128 + lane * 4;
                        float4 fv = *(const float4*)(rg + off);
                        float4 xv = *(const float4*)(rg + 512 + off);
                        fc[i*4+0]=fv.x; fc[i*4+1]=fv.y; fc[i*4+2]=fv.z; fc[i*4+3]=fv.w;
                        Bv[i*4+0]=fmaf(-fv.x,xv.x,xv.x); Bv[i*4+1]=fmaf(-fv.y,xv.y,xv.y);
                        Bv[i*4+2]=fmaf(-fv.z,xv.z,xv.z); Bv[i*4+3]=fmaf(-fv.w,xv.w,xv.w);
                    }
                }

                float mean = sum * (1.f / DD);
                float var  = fmaf(-mean, mean, ssq * (1.f / DD));
                float rstd = rsqrtf(var + EPSV);
                float t1   = -mean * rstd;
                #pragma unroll
                for (int j = 0; j < 16; j++)
                    h[j] = fmaf(gw[j], fmaf(hr[j], rstd, t1), gb[j] + h[j]);

                float* dst = g_xn + base + (size_t)s * DD;
                #pragma unroll
                for (int i = 0; i < 4; i++)
                    *(float4*)(dst + i * 128 + lane * 4) = *(float4*)(h + i * 4);

                if ((s & 7) == 7) {
                    __threadfence_block();
                    if (lane == 0) prog[0] = s + 1;
                }
            }
        } else {
            // ---- trailing finln consumers: warps 0..6, rows r = wid + 7k ----
            float gwf[16], gbf[16];
            ldrow16(gwf, lnfg, lane);
            ldrow16(gbf, lnfb, lane);
            const int slot = wid + 1;
            for (int r = wid; r < SS; r += 7) {
                if (lane == 0) { while (prog[0] <= r) __nanosleep(40); }
                __syncwarp();
                __threadfence_block();
                const float* p = g_xn + ((size_t)b * SS + r) * DD;
                float v[16];
                ldrow16(v, p, lane);
                float s4[4] = {0,0,0,0}, q4[4] = {0,0,0,0};
                #pragma unroll
                for (int j = 0; j < 16; j++) {
                    s4[j & 3] += v[j];
                    q4[j & 3] = fmaf(v[j], v[j], q4[j & 3]);
                }
                float sum = warp_sum((s4[0] + s4[1]) + (s4[2] + s4[3]));
                float ssq = warp_sum((q4[0] + q4[1]) + (q4[2] + q4[3]));
                float mean = sum * (1.f / DD);
                float var  = ssq * (1.f / DD) - mean * mean;
                float rstd = rsqrtf(var + EPSV);
                #pragma unroll
                for (int j = 0; j < 16; j++)
                    v[j] = fmaf((v[j] - mean) * rstd, gwf[j], gbf[j]);
                uint32_t w[8];
                pack_k16(v, w);
                uint4* dst = (uint4*)((char*)g_xh + (((size_t)b * SS + r) * DD + lane * 16) * 2);
                dst[0] = make_uint4(w[0], w[1], w[2], w[3]);
                dst[1] = make_uint4(w[4], w[5], w[6], w[7]);
                __threadfence();
                if (lane == 0) {
                    prog[slot] = r + 1;
                    int m = prog[1];
                    #pragma unroll
                    for (int i = 2; i < 8; i++) { int pv = prog[i]; m = (pv < m) ? pv : m; }
                    int k = m >> 7;                     // SEGLEN=128
                    if (k > 0) atomicMax(&g_prog[b], k);
                }
                __syncwarp();
            }
            // publish full completion (termination)
            __threadfence();
            if (lane == 0) {
                prog[slot] = SS;
                int m = prog[1];
                #pragma unroll
                for (int i = 2; i < 8; i++) { int pv = prog[i]; m = (pv < m) ? pv : m; }
                atomicMax(&g_prog[b], m >> 7);
            }
        }
        return;
    }

    // ================= persistent logits worker =================
    __shared__ int s_t;
    __shared__ int s_evict;
    if (tid == 0) {
        int ev = 0;
        #pragma unroll 1
        for (int i = 0; i < BB; i++) {
            int v;
            do { v = atomicAdd(&g_scansm[i], 0); if (v < 0) __nanosleep(20); } while (v < 0);
            if ((uint32_t)v == mysm) ev = 1;
        }
        s_evict = ev;
    }
    __syncthreads();
    if (s_evict) return;

    const uint32_t sb = smem_u32(smem);
    const int g = lane >> 2, t = lane & 3;
    const int warpM = wid >> 2, warpN = wid & 3;

    for (;;) {
        if (tid == 0) s_t = atomicAdd(&g_tick, 1);
        __syncthreads();
        int tkt = s_t;
        if (tkt >= NTILES) break;
        int seg = tkt / (NTILE_N * BB);
        int rem = tkt % (NTILE_N * BB);
        int b = rem & 7;
        int n0 = (rem >> 3) * 128;
        if (tid == 0) {
            int p;
            for (;;) {
                asm volatile("ld.global.acquire.gpu.s32 %0, [%1];" : "=r"(p) : "l"(&g_prog[b]));
                if (p > seg) break;
                __nanosleep(60);
            }
        }
        __syncthreads();
        const int m0 = b * SS + seg * SEGLEN;

        float acc[4][4][4];
        #pragma unroll
        for (int mt = 0; mt < 4; mt++)
            #pragma unroll
            for (int nt = 0; nt < 4; nt++)
                #pragma unroll
                for (int i = 0; i < 4; i++) acc[mt][nt][i] = 0.f;

        const char* gA = (const char*)g_xh + (size_t)m0 * DD * 2;
        const char* gB = (const char*)g_Eh + (size_t)n0 * DD * 2;

        auto LOAD = [&](int c) {
            uint32_t st = sb + (uint32_t)(c % 3) * STAGE_BYTES;
            int kb = c * 128;
            #pragma unroll
            for (int it = 0; it < 4; it++) {
                int idx = it * 256 + tid;
                int row = idx >> 3, q = idx & 7;
                uint32_t so = swz((uint32_t)(row * 128 + q * 16));
                cp16(st + so,         gA + (size_t)row * 1024 + kb + q * 16);
                cp16(st + 16384 + so, gB + (size_t)row * 1024 + kb + q * 16);
            }
            cpcommit();
        };
        auto COMP = [&](int buf) {
            const char* sA = smem + buf * STAGE_BYTES;
            const char* sB = smem + buf * STAGE_BYTES + 16384;
            #pragma unroll
            for (int kk = 0; kk < 4; kk++) {
                uint32_t a[4][4];
                #pragma unroll
                for (int mt = 0; mt < 4; mt++) {
                    int r0 = warpM * 64 + mt * 16 + g;
                    uint2 v1 = *(const uint2*)(sA + swz((uint32_t)(r0 * 128 + kk * 32 + t * 8)));
                    uint2 v2 = *(const uint2*)(sA + swz((uint32_t)((r0 + 8) * 128 + kk * 32 + t * 8)));
                    a[mt][0] = v1.x; a[mt][1] = v2.x; a[mt][2] = v1.y; a[mt][3] = v2.y;
                }
                #pragma unroll
                for (int nt = 0; nt < 4; nt++) {
                    int nr = warpN * 32 + nt * 8 + g;
                    uint2 bv = *(const uint2*)(sB + swz((uint32_t)(nr * 128 + kk * 32 + t * 8)));
                    #pragma unroll
                    for (int mt = 0; mt < 4; mt++)
                        mma16816(acc[mt][nt], a[mt], bv.x, bv.y);
                }
            }
        };

        LOAD(0); LOAD(1);
        #pragma unroll 1
        for (int c = 0; c < NCHUNK; c++) {
            if (c < NCHUNK - 1) cpwait<1>(); else cpwait<0>();
            __syncthreads();
            if (c + 2 < NCHUNK) LOAD(c + 2);
            COMP(c % 3);
        }

        #pragma unroll
        for (int mt = 0; mt < 4; mt++) {
            int mrow = m0 + warpM * 64 + mt * 16 + g;
            #pragma unroll
            for (int nt = 0; nt < 4; nt++) {
                int ncol = n0 + warpN * 32 + nt * 8 + 2 * t;
                float2 lo; lo.x = acc[mt][nt][0]; lo.y = acc[mt][nt][1];
                float2 hi; hi.x = acc[mt][nt][2]; hi.y = acc[mt][nt][3];
                *(float2*)(out + (size_t)mrow * VV + ncol) = lo;
                *(float2*)(out + (size_t)(mrow + 8) * VV + ncol) = hi;
            }
        }
        __syncthreads();   // protect smem stages + s_t before next iteration
    }
}

// ---------------- launch ----------------
extern "C" void kernel_launch(void* const* d_in, const int* in_sizes, int n_in,
                              void* d_out, int out_size) {
    const int*   tokens = (const int*)  d_in[0];
    const float* E      = (const float*)d_in[1];
    const float* W_ih   = (const float*)d_in[2];
    const float* b_h    = (const float*)d_in[3];
    const float* W1     = (const float*)d_in[4];
    const float* b1     = (const float*)d_in[5];
    const float* W2     = (const float*)d_in[6];
    const float* b2     = (const float*)d_in[7];
    const float* ln_g   = (const float*)d_in[8];
    const float* ln_b   = (const float*)d_in[9];
    const float* h0     = (const float*)d_in[10];
    const float* lnf_g  = (const float*)d_in[11];
    const float* lnf_b  = (const float*)d_in[12];
    float* out = (float*)d_out;

    static int init_done = 0;
    if (!init_done) {
        cudaFuncSetAttribute(k_p1_mma,  cudaFuncAttributeMaxDynamicSharedMemorySize, SMEM_MMA);
        cudaFuncSetAttribute(k_fused,   cudaFuncAttributeMaxDynamicSharedMemorySize, SMEM_MMA);
        init_done = 1;
    }

    k_conv_E<<<(VV*32)/256, 256>>>(E);
    k_conv_W<<<(3*DD*32)/256, 256>>>(W_ih, W1, W2);
    k_gather<<<BSZ/8, 256>>>(tokens, E);
    k_p1_mma<<<dim3(12, 64), 256, SMEM_MMA>>>(b_h, b1, b2);
    k_combine<<<4096, 256>>>();
    k_fused<<<BB + 288, 256, SMEM_MMA>>>(out, h0, ln_g, ln_b, lnf_g, lnf_b);
}